// round 4
// baseline (speedup 1.0000x reference)
#include <cuda_runtime.h>
#include <math.h>

// Shapes (fixed by the problem)
#define B_  16
#define C_  1024
#define H_  48
#define W_  48
#define N_  2304   // H*W
#define L_  512
#define CT_ 768
#define NS_ 3

// ---------------- scratch (device globals; no allocation allowed) ----------
__device__ float g_ktxt[B_ * L_ * C_];                 // (B,L,C)
__device__ float g_vtxt[B_ * L_ * C_];                 // (B,L,C)
__device__ float g_qT[B_ * C_ * N_];                   // (B,C,N)  q transposed
__device__ float g_logits[B_ * L_ * N_];               // (B,L,N)  scale k=1
__device__ float g_pool3[B_ * L_ * N_];                // (B,L,N)
__device__ float g_pool5[B_ * L_ * N_];                // (B,L,N)
__device__ float g_attn[B_ * L_ * N_];                 // (B,L,N)  combined attn^T
__device__ float g_bias[B_ * L_];                      // bq . k_txt[b,l]
__device__ float g_w[NS_];                             // softmax(lam)

// ---------------- generic tiled FP32 GEMM ----------------------------------
// C[m,n] = sum_k A[m,k] * B[k,n]   (+bias[n]) (+src[m,n])
// TA=false: A stored (M,K) row-major, lda=K
// TA=true : A stored (K,M) row-major, lda=M   (i.e. we use its transpose)
// B stored (K,N) row-major with ldb == N.  All dims multiples of tile sizes.
template <bool TA, bool BIAS, bool ADDSRC>
__global__ __launch_bounds__(256)
void sgemm_kernel(const float* __restrict__ A, const float* __restrict__ B,
                  float* __restrict__ C,
                  const float* __restrict__ bias, const float* __restrict__ src,
                  int N, int K, int lda,
                  long long strideA, long long strideB, long long strideC)
{
    constexpr int BM = 128, BN = 128, BK = 16;
    __shared__ float As[BK][BM];
    __shared__ float Bs[BK][BN];

    const int bz = blockIdx.z;
    A += strideA * bz;
    B += strideB * bz;
    C += strideC * bz;
    const float* S = nullptr;
    if (ADDSRC) S = src + strideC * bz;

    const int m0 = blockIdx.y * BM;
    const int n0 = blockIdx.x * BN;
    const int tid = threadIdx.x;
    const int tx = tid & 15;   // 0..15 -> n
    const int ty = tid >> 4;   // 0..15 -> m

    float acc[8][8];
#pragma unroll
    for (int i = 0; i < 8; i++)
#pragma unroll
        for (int j = 0; j < 8; j++) acc[i][j] = 0.f;

    for (int k0 = 0; k0 < K; k0 += BK) {
        if (TA) {
            // source (K,M): element (k,m) at A[(k0+k)*lda + m0+m]; contiguous in m
#pragma unroll
            for (int r = 0; r < 2; r++) {
                int f = tid + r * 256;          // 512 float4 total
                int k = f >> 5;                 // 32 float4 per k-row
                int mv = (f & 31) << 2;
                float4 v = *(const float4*)(A + (long long)(k0 + k) * lda + m0 + mv);
                *(float4*)&As[k][mv] = v;
            }
        } else {
            // source (M,K): element (m,k) at A[(m0+m)*lda + k0+k]; contiguous in k
#pragma unroll
            for (int r = 0; r < 2; r++) {
                int f = tid + r * 256;
                int m = f >> 2;                 // 4 float4 per m-row
                int kv = (f & 3) << 2;
                float4 v = *(const float4*)(A + (long long)(m0 + m) * lda + k0 + kv);
                As[kv + 0][m] = v.x;
                As[kv + 1][m] = v.y;
                As[kv + 2][m] = v.z;
                As[kv + 3][m] = v.w;
            }
        }
        // B tile (K,N), contiguous in n
#pragma unroll
        for (int r = 0; r < 2; r++) {
            int f = tid + r * 256;
            int k = f >> 5;
            int nv = (f & 31) << 2;
            float4 v = *(const float4*)(B + (long long)(k0 + k) * N + n0 + nv);
            *(float4*)&Bs[k][nv] = v;
        }
        __syncthreads();

#pragma unroll
        for (int kk = 0; kk < BK; kk++) {
            float a[8], b8[8];
            *(float4*)(a)     = *(const float4*)&As[kk][ty * 8];
            *(float4*)(a + 4) = *(const float4*)&As[kk][ty * 8 + 4];
            *(float4*)(b8)     = *(const float4*)&Bs[kk][tx * 8];
            *(float4*)(b8 + 4) = *(const float4*)&Bs[kk][tx * 8 + 4];
#pragma unroll
            for (int i = 0; i < 8; i++)
#pragma unroll
                for (int j = 0; j < 8; j++)
                    acc[i][j] = fmaf(a[i], b8[j], acc[i][j]);
        }
        __syncthreads();
    }

#pragma unroll
    for (int i = 0; i < 8; i++) {
        int m = m0 + ty * 8 + i;
        long long row = (long long)m * N + n0 + tx * 8;
#pragma unroll
        for (int jv = 0; jv < 2; jv++) {
            float4 o = make_float4(acc[i][jv * 4 + 0], acc[i][jv * 4 + 1],
                                   acc[i][jv * 4 + 2], acc[i][jv * 4 + 3]);
            if (BIAS) {
                float4 bb = *(const float4*)(bias + n0 + tx * 8 + jv * 4);
                o.x += bb.x; o.y += bb.y; o.z += bb.z; o.w += bb.w;
            }
            if (ADDSRC) {
                float4 s = *(const float4*)(S + row + jv * 4);
                o.x += s.x; o.y += s.y; o.z += s.z; o.w += s.w;
            }
            *(float4*)(C + row + jv * 4) = o;
        }
    }
}

// ---------------- softmax(lam) -> g_w ---------------------------------------
__global__ void prep_weights_kernel(const float* __restrict__ lam)
{
    if (threadIdx.x == 0) {
        float m = fmaxf(lam[0], fmaxf(lam[1], lam[2]));
        float e0 = __expf(lam[0] - m);
        float e1 = __expf(lam[1] - m);
        float e2 = __expf(lam[2] - m);
        float s = e0 + e1 + e2;
        g_w[0] = e0 / s; g_w[1] = e1 / s; g_w[2] = e2 / s;
    }
}

// ---------------- bias[b,l] = bq . k_txt[b,l,:] ------------------------------
__global__ __launch_bounds__(256) void bias_kernel(const float* __restrict__ bq)
{
    int row = blockIdx.x * 8 + (threadIdx.x >> 5);   // 0 .. B*L-1
    int lane = threadIdx.x & 31;
    const float* kr = g_ktxt + (long long)row * C_;
    float s = 0.f;
    for (int c = lane; c < C_; c += 32) s += bq[c] * kr[c];
#pragma unroll
    for (int off = 16; off > 0; off >>= 1) s += __shfl_xor_sync(0xffffffffu, s, off);
    if (lane == 0) g_bias[row] = s;
}

// ---------------- spatial box pooling of logits (k=3 and k=5) ----------------
__global__ __launch_bounds__(256) void pool_kernel()
{
    __shared__ float img[N_];
    const long long base = (long long)blockIdx.x * N_;   // one (b,l) image
    const float* src = g_logits + base;
    for (int i = threadIdx.x; i < N_; i += 256) img[i] = src[i];
    __syncthreads();

    for (int i = threadIdx.x; i < N_; i += 256) {
        int y = i / W_, x = i - y * W_;
        float s3 = 0.f, s5 = 0.f;
#pragma unroll
        for (int dy = -2; dy <= 2; dy++) {
            int yy = y + dy;
            if (yy < 0 || yy >= H_) continue;
#pragma unroll
            for (int dx = -2; dx <= 2; dx++) {
                int xx = x + dx;
                if (xx < 0 || xx >= W_) continue;
                float v = img[yy * W_ + xx];
                s5 += v;
                if (dy >= -1 && dy <= 1 && dx >= -1 && dx <= 1) s3 += v;
            }
        }
        g_pool3[base + i] = s3 * (1.f / 9.f);
        g_pool5[base + i] = s5 * (1.f / 25.f);
    }
}

// ---------------- 3-way softmax over L + weighted combine --------------------
// Block handles (b, 16 spatial positions). Data resident in smem (3 x 512 x 17).
#define SM_PAD 17
#define SM_PLANE (L_ * SM_PAD)
__global__ __launch_bounds__(512) void softmax_combine_kernel()
{
    extern __shared__ float sm[];           // 3 * 512 * 17 floats
    __shared__ float coef[NS_][16];

    const int b = blockIdx.y;
    const int n0 = blockIdx.x * 16;
    const int tid = threadIdx.x;
    const float sc = 0.03125f;              // C^{-1/2} = 1/32 exactly

    // load + bias + scale
    for (int idx = tid; idx < L_ * 16; idx += 512) {
        int l = idx >> 4, j = idx & 15;
        float bias = g_bias[b * L_ + l];
        long long g = ((long long)(b * L_ + l)) * N_ + n0 + j;
        sm[0 * SM_PLANE + l * SM_PAD + j] = (g_logits[g] + bias) * sc;
        sm[1 * SM_PLANE + l * SM_PAD + j] = (g_pool3[g]  + bias) * sc;
        sm[2 * SM_PLANE + l * SM_PAD + j] = (g_pool5[g]  + bias) * sc;
    }
    __syncthreads();

    // softmax over l for each of the 48 (scale, j) columns; warp per column
    const int warp = tid >> 5, lane = tid & 31;
    for (int col = warp; col < NS_ * 16; col += 16) {
        int s = col >> 4, j = col & 15;
        float* base = sm + s * SM_PLANE + j;
        float vals[16];
        float mx = -1e30f;
#pragma unroll
        for (int r = 0; r < 16; r++) {
            vals[r] = base[(lane + r * 32) * SM_PAD];
            mx = fmaxf(mx, vals[r]);
        }
#pragma unroll
        for (int off = 16; off > 0; off >>= 1)
            mx = fmaxf(mx, __shfl_xor_sync(0xffffffffu, mx, off));
        float ssum = 0.f;
#pragma unroll
        for (int r = 0; r < 16; r++) {
            float e = __expf(vals[r] - mx);
            base[(lane + r * 32) * SM_PAD] = e;
            ssum += e;
        }
#pragma unroll
        for (int off = 16; off > 0; off >>= 1)
            ssum += __shfl_xor_sync(0xffffffffu, ssum, off);
        if (lane == 0) coef[s][j] = g_w[s] / ssum;
    }
    __syncthreads();

    // combined attention, stored transposed: g_attn[b,l,n]
    for (int idx = tid; idx < L_ * 16; idx += 512) {
        int l = idx >> 4, j = idx & 15;
        float v = sm[0 * SM_PLANE + l * SM_PAD + j] * coef[0][j]
                + sm[1 * SM_PLANE + l * SM_PAD + j] * coef[1][j]
                + sm[2 * SM_PLANE + l * SM_PAD + j] * coef[2][j];
        g_attn[((long long)(b * L_ + l)) * N_ + n0 + j] = v;
    }
}

// ---------------- t_tok passthrough -----------------------------------------
__global__ __launch_bounds__(256) void copy_kernel(const float4* __restrict__ src,
                                                   float4* __restrict__ dst, int n4)
{
    int i = blockIdx.x * 256 + threadIdx.x;
    if (i < n4) dst[i] = src[i];
}

// ---------------- host ------------------------------------------------------
extern "C" void kernel_launch(void* const* d_in, const int* in_sizes, int n_in,
                              void* d_out, int out_size)
{
    const float* v_feat = (const float*)d_in[0];   // (B,C,H,W)
    const float* t_tok  = (const float*)d_in[1];   // (B,L,Ct)
    const float* Wq     = (const float*)d_in[2];   // (C,C)
    const float* bq     = (const float*)d_in[3];
    const float* Wk     = (const float*)d_in[4];   // (Ct,C)
    const float* bk     = (const float*)d_in[5];
    const float* Wv     = (const float*)d_in[6];   // (Ct,C)
    const float* bv     = (const float*)d_in[7];
    const float* lam    = (const float*)d_in[8];   // (3,)
    float* out = (float*)d_out;

    float *p_ktxt, *p_vtxt, *p_qT, *p_logits, *p_attn;
    cudaGetSymbolAddress((void**)&p_ktxt,   g_ktxt);
    cudaGetSymbolAddress((void**)&p_vtxt,   g_vtxt);
    cudaGetSymbolAddress((void**)&p_qT,     g_qT);
    cudaGetSymbolAddress((void**)&p_logits, g_logits);
    cudaGetSymbolAddress((void**)&p_attn,   g_attn);

    prep_weights_kernel<<<1, 32>>>(lam);

    // k_txt = t_tok @ Wk + bk     (M=B*L=8192, N=C=1024, K=Ct=768)
    sgemm_kernel<false, true, false><<<dim3(C_ / 128, (B_ * L_) / 128, 1), 256>>>(
        t_tok, Wk, p_ktxt, bk, nullptr, C_, CT_, CT_, 0, 0, 0);
    // v_txt = t_tok @ Wv + bv
    sgemm_kernel<false, true, false><<<dim3(C_ / 128, (B_ * L_) / 128, 1), 256>>>(
        t_tok, Wv, p_vtxt, bv, nullptr, C_, CT_, CT_, 0, 0, 0);

    // bias[b,l] = bq . k_txt[b,l]
    bias_kernel<<<(B_ * L_) / 8, 256>>>(bq);

    // qT[b] = Wq^T @ v_feat[b]    (M=C, N=N_, K=C), A=Wq accessed transposed
    sgemm_kernel<true, false, false><<<dim3(N_ / 128, C_ / 128, B_), 256>>>(
        Wq, v_feat, p_qT, nullptr, nullptr, N_, C_, C_,
        0, (long long)C_ * N_, (long long)C_ * N_);

    // logits[b] = k_txt[b] @ qT[b]  (M=L, N=N_, K=C)
    sgemm_kernel<false, false, false><<<dim3(N_ / 128, L_ / 128, B_), 256>>>(
        p_ktxt, p_qT, p_logits, nullptr, nullptr, N_, C_, C_,
        (long long)L_ * C_, (long long)C_ * N_, (long long)L_ * N_);

    // spatial pooling of logits for k=3,5
    pool_kernel<<<B_ * L_, 256>>>();

    // 3-way softmax over L + weighted combine -> g_attn (B,L,N)
    size_t smem = (size_t)NS_ * SM_PLANE * sizeof(float);
    cudaFuncSetAttribute(softmax_combine_kernel,
                         cudaFuncAttributeMaxDynamicSharedMemorySize, (int)smem);
    softmax_combine_kernel<<<dim3(N_ / 16, B_), 512, smem>>>();

    // out_vis[b] = v_txt[b]^T @ attn[b] + v_feat[b]   (M=C, N=N_, K=L)
    sgemm_kernel<true, false, true><<<dim3(N_ / 128, C_ / 128, B_), 256>>>(
        p_vtxt, p_attn, out, nullptr, v_feat, N_, L_, C_,
        (long long)L_ * C_, (long long)L_ * N_, (long long)C_ * N_);

    // t_tok passthrough into tail of output
    int n4 = (B_ * L_ * CT_) / 4;
    copy_kernel<<<(n4 + 255) / 256, 256>>>(
        (const float4*)t_tok, (float4*)(out + (size_t)B_ * C_ * N_), n4);
}

// round 10
// speedup vs baseline: 4.0506x; 4.0506x over previous
#include <cuda_runtime.h>
#include <cuda_bf16.h>
#include <cstdint>
#include <math.h>

// Shapes (fixed by the problem)
#define B_  16
#define C_  1024
#define H_  48
#define W_  48
#define N_  2304   // H*W
#define L_  512
#define CT_ 768
#define NS_ 3

// ---------------- scratch (device globals; no allocation allowed) ----------
__device__ __nv_bfloat16 g_ttok_bf[B_ * L_ * CT_];     // (B,L,Ct)
__device__ __nv_bfloat16 g_WkT[C_ * CT_];              // (C,Ct)
__device__ __nv_bfloat16 g_WvT[C_ * CT_];              // (C,Ct)
__device__ __nv_bfloat16 g_WqT[C_ * C_];               // (Cout,Cin)
__device__ __nv_bfloat16 g_ktxt_bf[B_ * L_ * C_];      // (B,L,C)
__device__ __nv_bfloat16 g_vtxt_bf[B_ * L_ * C_];      // (B,L,C)
__device__ __nv_bfloat16 g_vtxtT_bf[B_ * C_ * L_];     // (B,C,L)
__device__ __nv_bfloat16 g_vflat_bf[B_ * N_ * C_];     // (B,N,C)
__device__ __nv_bfloat16 g_q_bf[B_ * N_ * C_];         // (B,N,C)  q (no bias)
__device__ __nv_bfloat16 g_attnT_bf[B_ * N_ * L_];     // (B,N,L)  combined attn^T
__device__ float g_logits[B_ * L_ * N_];               // (B,L,N)  scale k=1
__device__ float g_pool3[B_ * L_ * N_];                // (B,L,N)
__device__ float g_pool5[B_ * L_ * N_];                // (B,L,N)
__device__ float g_bias[B_ * L_];                      // bq . k_txt[b,l]
__device__ float g_w[NS_];                             // softmax(lam)

// ======================= helpers ============================================
__device__ __forceinline__ uint32_t smem_u32(const void* p) {
    uint32_t a;
    asm("{ .reg .u64 t; cvta.to.shared.u64 t, %1; cvt.u32.u64 %0, t; }"
        : "=r"(a) : "l"(p));
    return a;
}
__device__ __forceinline__ void ldsm_x4(uint32_t* f, uint32_t addr) {
    asm volatile("ldmatrix.sync.aligned.m8n8.x4.shared.b16 {%0,%1,%2,%3}, [%4];"
                 : "=r"(f[0]), "=r"(f[1]), "=r"(f[2]), "=r"(f[3]) : "r"(addr));
}
__device__ __forceinline__ void mma16816(float* d, const uint32_t* a,
                                         uint32_t b0, uint32_t b1) {
    asm volatile("mma.sync.aligned.m16n8k16.row.col.f32.bf16.bf16.f32 "
                 "{%0,%1,%2,%3}, {%4,%5,%6,%7}, {%8,%9}, {%0,%1,%2,%3};"
                 : "+f"(d[0]), "+f"(d[1]), "+f"(d[2]), "+f"(d[3])
                 : "r"(a[0]), "r"(a[1]), "r"(a[2]), "r"(a[3]), "r"(b0), "r"(b1));
}
__device__ __forceinline__ void cp_async16(uint32_t dst, const void* src) {
    asm volatile("cp.async.cg.shared.global [%0], [%1], 16;" :: "r"(dst), "l"(src));
}

// ======================= HMMA bf16 batched GEMM =============================
// C[m,n] = sum_k A[m,k] * Bop[n,k]; A (M,K) bf16 K-major, Bop (N,K) bf16 K-major.
// CTA tile 128x128x32, 256 threads (8 warps, 2x4 of 64x32 warp tiles).
// EPI: 0 = bf16 out (+bias[n] if BIAS), 1 = fp32 out, 2 = fp32 out + Res add.
#define BM 128
#define BN 128
#define BKK 32
#define AST 40   // bf16 elems per smem row (32 + 8 pad) => 80B stride

template <int EPI, bool BIAS>
__global__ __launch_bounds__(256)
void mm_bf16(const __nv_bfloat16* __restrict__ A, const __nv_bfloat16* __restrict__ Bm,
             void* __restrict__ Out, const float* __restrict__ bias,
             const float* __restrict__ Res,
             int N, int K, long long sA, long long sB, long long sO)
{
    __shared__ __nv_bfloat16 As[2][BM * AST];
    __shared__ __nv_bfloat16 Bs[2][BN * AST];

    const int b = blockIdx.z;
    A  += sA * b;
    Bm += sB * b;
    const int m0 = blockIdx.y * BM;
    const int n0 = blockIdx.x * BN;
    const int tid = threadIdx.x, wid = tid >> 5, lane = tid & 31;
    const int wm = (wid & 1) * 64;    // warp m offset within tile
    const int wn = (wid >> 1) * 32;   // warp n offset within tile

    float acc[4][4][4];
#pragma unroll
    for (int i = 0; i < 4; i++)
#pragma unroll
        for (int j = 0; j < 4; j++)
#pragma unroll
            for (int r = 0; r < 4; r++) acc[i][j][r] = 0.f;

    // loader mapping: 512 chunks of 16B per operand tile, 2 per thread
    const int lr0 = tid >> 1;                 // unused placeholder kept minimal
    (void)lr0;
    const int nK = K / BKK;

    // ldmatrix source addresses (fixed per thread, vary by buf/ks)
    const int lr = lane & 15;
    const int lc = (lane >> 4) * 8;

    // ---- prologue: load tile 0 into buf 0
    {
        const long long k0 = 0;
#pragma unroll
        for (int i = 0; i < 2; i++) {
            int f = tid + i * 256;
            int row = f >> 2, ch = f & 3;
            cp_async16(smem_u32(&As[0][row * AST + ch * 8]),
                       A + (long long)(m0 + row) * K + k0 + ch * 8);
            cp_async16(smem_u32(&Bs[0][row * AST + ch * 8]),
                       Bm + (long long)(n0 + row) * K + k0 + ch * 8);
        }
        asm volatile("cp.async.commit_group;");
    }

    for (int c = 0; c < nK; c++) {
        const int buf = c & 1;
        if (c + 1 < nK) {
            const int nb = (c + 1) & 1;
            const long long k0 = (long long)(c + 1) * BKK;
#pragma unroll
            for (int i = 0; i < 2; i++) {
                int f = tid + i * 256;
                int row = f >> 2, ch = f & 3;
                cp_async16(smem_u32(&As[nb][row * AST + ch * 8]),
                           A + (long long)(m0 + row) * K + k0 + ch * 8);
                cp_async16(smem_u32(&Bs[nb][row * AST + ch * 8]),
                           Bm + (long long)(n0 + row) * K + k0 + ch * 8);
            }
            asm volatile("cp.async.commit_group;");
            asm volatile("cp.async.wait_group 1;");
        } else {
            asm volatile("cp.async.wait_group 0;");
        }
        __syncthreads();

#pragma unroll
        for (int ks = 0; ks < 2; ks++) {
            uint32_t af[4][4], bfq[2][4];
#pragma unroll
            for (int mt = 0; mt < 4; mt++) {
                uint32_t addr = smem_u32(&As[buf][(wm + mt * 16 + lr) * AST + ks * 16 + lc]);
                ldsm_x4(af[mt], addr);
            }
#pragma unroll
            for (int ng = 0; ng < 2; ng++) {
                uint32_t addr = smem_u32(&Bs[buf][(wn + ng * 16 + lr) * AST + ks * 16 + lc]);
                ldsm_x4(bfq[ng], addr);
            }
#pragma unroll
            for (int mt = 0; mt < 4; mt++)
#pragma unroll
                for (int nt = 0; nt < 4; nt++) {
                    const int ng = nt >> 1, sub = nt & 1;
                    mma16816(acc[mt][nt], af[mt], bfq[ng][sub], bfq[ng][sub + 2]);
                }
        }
        __syncthreads();
    }

    // ---- epilogue (fragment layout: lane = 4*g + tg; rows g, g+8; cols 2tg,2tg+1)
    const int g = lane >> 2, tg = lane & 3;
#pragma unroll
    for (int mt = 0; mt < 4; mt++) {
#pragma unroll
        for (int nt = 0; nt < 4; nt++) {
            const int row = m0 + wm + mt * 16 + g;
            const int col = n0 + wn + nt * 8 + 2 * tg;
            const long long o0 = (long long)row * N + col;
            const long long o1 = (long long)(row + 8) * N + col;
            float x0 = acc[mt][nt][0], x1 = acc[mt][nt][1];
            float x2 = acc[mt][nt][2], x3 = acc[mt][nt][3];
            if (EPI == 0) {
                if (BIAS) {
                    float b0 = bias[col], b1 = bias[col + 1];
                    x0 += b0; x1 += b1; x2 += b0; x3 += b1;
                }
                __nv_bfloat16* o = (__nv_bfloat16*)Out + (long long)b * sO;
                *(__nv_bfloat162*)(o + o0) = __floats2bfloat162_rn(x0, x1);
                *(__nv_bfloat162*)(o + o1) = __floats2bfloat162_rn(x2, x3);
            } else {
                float* o = (float*)Out + (long long)b * sO;
                if (EPI == 2) {
                    const float* rs = Res + (long long)b * sO;
                    float2 r0 = *(const float2*)(rs + o0);
                    float2 r1 = *(const float2*)(rs + o1);
                    x0 += r0.x; x1 += r0.y; x2 += r1.x; x3 += r1.y;
                }
                *(float2*)(o + o0) = make_float2(x0, x1);
                *(float2*)(o + o1) = make_float2(x2, x3);
            }
        }
    }
}

// ---------------- elementwise fp32 -> bf16 convert ---------------------------
__global__ __launch_bounds__(256) void cvt_bf16_kernel(const float4* __restrict__ in,
                                                       __nv_bfloat162* __restrict__ out,
                                                       int n4)
{
    int i = blockIdx.x * 256 + threadIdx.x;
    if (i < n4) {
        float4 v = in[i];
        out[2 * i]     = __floats2bfloat162_rn(v.x, v.y);
        out[2 * i + 1] = __floats2bfloat162_rn(v.z, v.w);
    }
}

// ---------------- tiled transpose (R,C) -> (C,R) bf16 ------------------------
template <typename Tin>
__global__ __launch_bounds__(256)
void transpose_bf16_kernel(const Tin* __restrict__ in, __nv_bfloat16* __restrict__ out,
                           int R, int Cc, long long sIn, long long sOut)
{
    __shared__ float t[32][33];
    const int b = blockIdx.z;
    const Tin* I = in + sIn * b;
    __nv_bfloat16* O = out + sOut * b;
    const int c0 = blockIdx.x * 32, r0 = blockIdx.y * 32;
    const int tx = threadIdx.x & 31, ty = threadIdx.x >> 5;
#pragma unroll
    for (int i = 0; i < 32; i += 8)
        t[ty + i][tx] = (float)I[(long long)(r0 + ty + i) * Cc + c0 + tx];
    __syncthreads();
#pragma unroll
    for (int i = 0; i < 32; i += 8)
        O[(long long)(c0 + ty + i) * R + r0 + tx] = __float2bfloat16(t[tx][ty + i]);
}

// ---------------- softmax(lam) -> g_w ---------------------------------------
__global__ void prep_weights_kernel(const float* __restrict__ lam)
{
    if (threadIdx.x == 0) {
        float m = fmaxf(lam[0], fmaxf(lam[1], lam[2]));
        float e0 = __expf(lam[0] - m);
        float e1 = __expf(lam[1] - m);
        float e2 = __expf(lam[2] - m);
        float s = e0 + e1 + e2;
        g_w[0] = e0 / s; g_w[1] = e1 / s; g_w[2] = e2 / s;
    }
}

// ---------------- bias[b,l] = bq . k_txt[b,l,:]  (bf16 k_txt) -----------------
__global__ __launch_bounds__(256) void bias_kernel(const float* __restrict__ bq)
{
    int row = blockIdx.x * 8 + (threadIdx.x >> 5);
    int lane = threadIdx.x & 31;
    const __nv_bfloat16* kr = g_ktxt_bf + (long long)row * C_;
    float s = 0.f;
    for (int c = lane; c < C_; c += 32) s += bq[c] * __bfloat162float(kr[c]);
#pragma unroll
    for (int off = 16; off > 0; off >>= 1) s += __shfl_xor_sync(0xffffffffu, s, off);
    if (lane == 0) g_bias[row] = s;
}

// ---------------- spatial box pooling of logits (k=3 and k=5) ----------------
__global__ __launch_bounds__(256) void pool_kernel()
{
    __shared__ float img[N_];
    const long long base = (long long)blockIdx.x * N_;
    const float* src = g_logits + base;
    for (int i = threadIdx.x; i < N_; i += 256) img[i] = src[i];
    __syncthreads();

    for (int i = threadIdx.x; i < N_; i += 256) {
        int y = i / W_, x = i - y * W_;
        float s3 = 0.f, s5 = 0.f;
#pragma unroll
        for (int dy = -2; dy <= 2; dy++) {
            int yy = y + dy;
            if (yy < 0 || yy >= H_) continue;
#pragma unroll
            for (int dx = -2; dx <= 2; dx++) {
                int xx = x + dx;
                if (xx < 0 || xx >= W_) continue;
                float v = img[yy * W_ + xx];
                s5 += v;
                if (dy >= -1 && dy <= 1 && dx >= -1 && dx <= 1) s3 += v;
            }
        }
        g_pool3[base + i] = s3 * (1.f / 9.f);
        g_pool5[base + i] = s5 * (1.f / 25.f);
    }
}

// ---------------- 3-way softmax over L + weighted combine -> attn^T bf16 -----
#define SM_PAD 17
#define SM_PLANE (L_ * SM_PAD)
__global__ __launch_bounds__(512) void softmax_combine_kernel()
{
    extern __shared__ float sm[];           // 3 * 512 * 17 floats
    __shared__ float coef[NS_][16];

    const int b = blockIdx.y;
    const int n0 = blockIdx.x * 16;
    const int tid = threadIdx.x;
    const float sc = 0.03125f;              // C^{-1/2}

    for (int idx = tid; idx < L_ * 16; idx += 512) {
        int l = idx >> 4, j = idx & 15;
        float bias = g_bias[b * L_ + l];
        long long g = ((long long)(b * L_ + l)) * N_ + n0 + j;
        sm[0 * SM_PLANE + l * SM_PAD + j] = (g_logits[g] + bias) * sc;
        sm[1 * SM_PLANE + l * SM_PAD + j] = (g_pool3[g]  + bias) * sc;
        sm[2 * SM_PLANE + l * SM_PAD + j] = (g_pool5[g]  + bias) * sc;
    }
    __syncthreads();

    const int warp = tid >> 5, lane = tid & 31;
    for (int col = warp; col < NS_ * 16; col += 16) {
        int s = col >> 4, j = col & 15;
        float* base = sm + s * SM_PLANE + j;
        float vals[16];
        float mx = -1e30f;
#pragma unroll
        for (int r = 0; r < 16; r++) {
            vals[r] = base[(lane + r * 32) * SM_PAD];
            mx = fmaxf(mx, vals[r]);
        }
#pragma unroll
        for (int off = 16; off > 0; off >>= 1)
            mx = fmaxf(mx, __shfl_xor_sync(0xffffffffu, mx, off));
        float ssum = 0.f;
#pragma unroll
        for (int r = 0; r < 16; r++) {
            float e = __expf(vals[r] - mx);
            base[(lane + r * 32) * SM_PAD] = e;
            ssum += e;
        }
#pragma unroll
        for (int off = 16; off > 0; off >>= 1)
            ssum += __shfl_xor_sync(0xffffffffu, ssum, off);
        if (lane == 0) coef[s][j] = g_w[s] / ssum;
    }
    __syncthreads();

    // write attn^T (B, N_, L) bf16; one warp per spatial column, coalesced over l
    {
        const int j = warp;                 // 16 warps, one j each
        const float c0 = coef[0][j], c1 = coef[1][j], c2 = coef[2][j];
        __nv_bfloat16* dst = g_attnT_bf + ((long long)(b * N_ + n0 + j)) * L_;
        for (int l = lane; l < L_; l += 32) {
            float v = sm[0 * SM_PLANE + l * SM_PAD + j] * c0
                    + sm[1 * SM_PLANE + l * SM_PAD + j] * c1
                    + sm[2 * SM_PLANE + l * SM_PAD + j] * c2;
            dst[l] = __float2bfloat16(v);
        }
    }
}

// ---------------- t_tok passthrough -----------------------------------------
__global__ __launch_bounds__(256) void copy_kernel(const float4* __restrict__ src,
                                                   float4* __restrict__ dst, int n4)
{
    int i = blockIdx.x * 256 + threadIdx.x;
    if (i < n4) dst[i] = src[i];
}

// ---------------- host ------------------------------------------------------
extern "C" void kernel_launch(void* const* d_in, const int* in_sizes, int n_in,
                              void* d_out, int out_size)
{
    const float* v_feat = (const float*)d_in[0];   // (B,C,H,W)
    const float* t_tok  = (const float*)d_in[1];   // (B,L,Ct)
    const float* Wq     = (const float*)d_in[2];   // (C,C)
    const float* bq     = (const float*)d_in[3];
    const float* Wk     = (const float*)d_in[4];   // (Ct,C)
    const float* bk     = (const float*)d_in[5];
    const float* Wv     = (const float*)d_in[6];   // (Ct,C)
    const float* bv     = (const float*)d_in[7];
    const float* lam    = (const float*)d_in[8];   // (3,)
    float* out = (float*)d_out;

    __nv_bfloat16 *p_ttok, *p_WkT, *p_WvT, *p_WqT, *p_ktxt, *p_vtxt, *p_vtxtT,
                  *p_vflat, *p_q, *p_attnT;
    float *p_logits;
    cudaGetSymbolAddress((void**)&p_ttok,  g_ttok_bf);
    cudaGetSymbolAddress((void**)&p_WkT,   g_WkT);
    cudaGetSymbolAddress((void**)&p_WvT,   g_WvT);
    cudaGetSymbolAddress((void**)&p_WqT,   g_WqT);
    cudaGetSymbolAddress((void**)&p_ktxt,  g_ktxt_bf);
    cudaGetSymbolAddress((void**)&p_vtxt,  g_vtxt_bf);
    cudaGetSymbolAddress((void**)&p_vtxtT, g_vtxtT_bf);
    cudaGetSymbolAddress((void**)&p_vflat, g_vflat_bf);
    cudaGetSymbolAddress((void**)&p_q,     g_q_bf);
    cudaGetSymbolAddress((void**)&p_attnT, g_attnT_bf);
    cudaGetSymbolAddress((void**)&p_logits, g_logits);

    prep_weights_kernel<<<1, 32>>>(lam);

    // convert t_tok -> bf16
    {
        int n4 = (B_ * L_ * CT_) / 4;
        cvt_bf16_kernel<<<(n4 + 255) / 256, 256>>>((const float4*)t_tok,
                                                   (__nv_bfloat162*)p_ttok, n4);
    }
    // transpose weights -> bf16 (Cout, Cin)
    transpose_bf16_kernel<float><<<dim3(C_ / 32, CT_ / 32, 1), 256>>>(Wk, p_WkT, CT_, C_, 0, 0);
    transpose_bf16_kernel<float><<<dim3(C_ / 32, CT_ / 32, 1), 256>>>(Wv, p_WvT, CT_, C_, 0, 0);
    transpose_bf16_kernel<float><<<dim3(C_ / 32, C_ / 32, 1), 256>>>(Wq, p_WqT, C_, C_, 0, 0);
    // v_feat (B,C,N) -> v_flat (B,N,C) bf16
    transpose_bf16_kernel<float><<<dim3(N_ / 32, C_ / 32, B_), 256>>>(
        v_feat, p_vflat, C_, N_, (long long)C_ * N_, (long long)N_ * C_);

    // k_txt = t_tok @ Wk + bk  -> bf16 (B*L, C)
    mm_bf16<0, true><<<dim3(C_ / BN, (B_ * L_) / BM, 1), 256>>>(
        p_ttok, p_WkT, p_ktxt, bk, nullptr, C_, CT_, 0, 0, 0);
    // v_txt = t_tok @ Wv + bv  -> bf16 (B*L, C)
    mm_bf16<0, true><<<dim3(C_ / BN, (B_ * L_) / BM, 1), 256>>>(
        p_ttok, p_WvT, p_vtxt, bv, nullptr, C_, CT_, 0, 0, 0);

    bias_kernel<<<(B_ * L_) / 8, 256>>>(bq);

    // v_txt (B,L,C) -> v_txt^T (B,C,L) bf16
    transpose_bf16_kernel<__nv_bfloat16><<<dim3(C_ / 32, L_ / 32, B_), 256>>>(
        p_vtxt, p_vtxtT, L_, C_, (long long)L_ * C_, (long long)C_ * L_);

    // q[b] = v_flat[b] @ Wq  -> bf16 (B,N,C)   (no bias; handled post-pool)
    mm_bf16<0, false><<<dim3(C_ / BN, N_ / BM, B_), 256>>>(
        p_vflat, p_WqT, p_q, nullptr, nullptr, C_, C_,
        (long long)N_ * C_, 0, (long long)N_ * C_);

    // logits[b] = k_txt[b] @ q[b]^T  -> fp32 (B,L,N)
    mm_bf16<1, false><<<dim3(N_ / BN, L_ / BM, B_), 256>>>(
        p_ktxt, p_q, p_logits, nullptr, nullptr, N_, C_,
        (long long)L_ * C_, (long long)N_ * C_, (long long)L_ * N_);

    pool_kernel<<<B_ * L_, 256>>>();

    size_t smem = (size_t)NS_ * SM_PLANE * sizeof(float);
    cudaFuncSetAttribute(softmax_combine_kernel,
                         cudaFuncAttributeMaxDynamicSharedMemorySize, (int)smem);
    softmax_combine_kernel<<<dim3(N_ / 16, B_), 512, smem>>>();

    // out_vis[b] = v_txt[b]^T @ attn[b] + v_feat[b]  -> fp32 (B,C,N)
    mm_bf16<2, false><<<dim3(N_ / BN, C_ / BM, B_), 256>>>(
        p_vtxtT, p_attnT, out, nullptr, v_feat, N_, L_,
        (long long)C_ * L_, (long long)N_ * L_, (long long)C_ * N_);

    // t_tok passthrough
    int n4 = (B_ * L_ * CT_) / 4;
    copy_kernel<<<(n4 + 255) / 256, 256>>>(
        (const float4*)t_tok, (float4*)(out + (size_t)B_ * C_ * N_), n4);
}

// round 11
// speedup vs baseline: 4.7879x; 1.1820x over previous
#include <cuda_runtime.h>
#include <cuda_bf16.h>
#include <cstdint>
#include <math.h>

// Shapes (fixed by the problem)
#define B_  16
#define C_  1024
#define H_  48
#define W_  48
#define N_  2304   // H*W
#define L_  512
#define CT_ 768
#define NS_ 3

// ---------------- scratch (device globals; no allocation allowed) ----------
__device__ __nv_bfloat16 g_ttok_bf[B_ * L_ * CT_];     // (B,L,Ct)
__device__ __nv_bfloat16 g_WkT[C_ * CT_];              // (C,Ct)
__device__ __nv_bfloat16 g_WvT[C_ * CT_];              // (C,Ct)
__device__ __nv_bfloat16 g_Wq_bf[C_ * C_];             // (Cin,Cout) original layout
__device__ __nv_bfloat16 g_ktxt_bf[B_ * L_ * C_];      // (B,L,C)
__device__ __nv_bfloat16 g_vtxt_bf[B_ * L_ * C_];      // (B,L,C)
__device__ __nv_bfloat16 g_vtxtT_bf[B_ * C_ * L_];     // (B,C,L)
__device__ __nv_bfloat16 g_vflat_bf[B_ * N_ * C_];     // (B,N,C)
__device__ __nv_bfloat16 g_kq_bf[B_ * L_ * C_];        // (B,L,C)  k_txt @ Wq^T
__device__ __nv_bfloat16 g_attnT_bf[B_ * N_ * L_];     // (B,N,L)  combined attn^T
__device__ float g_logits[B_ * L_ * N_];               // (B,L,N)  scale k=1
__device__ float g_pool3[B_ * L_ * N_];                // (B,L,N)
__device__ float g_pool5[B_ * L_ * N_];                // (B,L,N)
__device__ float g_bias[B_ * L_];                      // bq . k_txt[b,l]
__device__ float g_w[NS_];                             // softmax(lam)

// ======================= helpers ============================================
__device__ __forceinline__ uint32_t smem_u32(const void* p) {
    uint32_t a;
    asm("{ .reg .u64 t; cvta.to.shared.u64 t, %1; cvt.u32.u64 %0, t; }"
        : "=r"(a) : "l"(p));
    return a;
}
__device__ __forceinline__ void ldsm_x4(uint32_t* f, uint32_t addr) {
    asm volatile("ldmatrix.sync.aligned.m8n8.x4.shared.b16 {%0,%1,%2,%3}, [%4];"
                 : "=r"(f[0]), "=r"(f[1]), "=r"(f[2]), "=r"(f[3]) : "r"(addr));
}
__device__ __forceinline__ void mma16816(float* d, const uint32_t* a,
                                         uint32_t b0, uint32_t b1) {
    asm volatile("mma.sync.aligned.m16n8k16.row.col.f32.bf16.bf16.f32 "
                 "{%0,%1,%2,%3}, {%4,%5,%6,%7}, {%8,%9}, {%0,%1,%2,%3};"
                 : "+f"(d[0]), "+f"(d[1]), "+f"(d[2]), "+f"(d[3])
                 : "r"(a[0]), "r"(a[1]), "r"(a[2]), "r"(a[3]), "r"(b0), "r"(b1));
}
__device__ __forceinline__ void cp_async16(uint32_t dst, const void* src) {
    asm volatile("cp.async.cg.shared.global [%0], [%1], 16;" :: "r"(dst), "l"(src));
}

// ======================= HMMA bf16 batched GEMM =============================
// C[m,n] = sum_k A[m,k] * Bop[n,k]; A (M,K) bf16 K-major, Bop (N,K) bf16 K-major.
// CTA tile 128x256x32, 3-stage cp.async pipeline, 256 threads
// (8 warps, 2x4 grid of 64x64 warp tiles).
// EPI: 0 = bf16 out (+bias[n] if BIAS), 1 = fp32 out, 2 = fp32 out + Res add.
#define BM 128
#define BN 256
#define BKK 32
#define AST 40   // bf16 elems per smem row (32 + 8 pad) => 80B stride
#define MM_STAGES 3
#define MM_SMEM (MM_STAGES * (BM + BN) * AST * 2)   // 92160 bytes

template <int EPI, bool BIAS>
__global__ __launch_bounds__(256)
void mm_bf16(const __nv_bfloat16* __restrict__ A, const __nv_bfloat16* __restrict__ Bm,
             void* __restrict__ Out, const float* __restrict__ bias,
             const float* __restrict__ Res,
             int N, int K, long long sA, long long sB, long long sO)
{
    extern __shared__ __nv_bfloat16 dsm[];
    __nv_bfloat16* As = dsm;                       // [3][BM*AST]
    __nv_bfloat16* Bs = dsm + MM_STAGES * BM * AST; // [3][BN*AST]

    const int b = blockIdx.z;
    A  += sA * b;
    Bm += sB * b;
    const int m0 = blockIdx.y * BM;
    const int n0 = blockIdx.x * BN;
    const int tid = threadIdx.x, wid = tid >> 5, lane = tid & 31;
    const int wm = (wid & 1) * 64;    // warp m offset within tile
    const int wn = (wid >> 1) * 64;   // warp n offset within tile

    float acc[4][8][4];
#pragma unroll
    for (int i = 0; i < 4; i++)
#pragma unroll
        for (int j = 0; j < 8; j++)
#pragma unroll
            for (int r = 0; r < 4; r++) acc[i][j][r] = 0.f;

    const int nK = K / BKK;
    const int lr = lane & 15;
    const int lc = (lane >> 4) * 8;

    // stage loader: A = 512 16B-chunks (2/thread), B = 1024 (4/thread)
    auto load_stage = [&](int st, long long k0) {
        __nv_bfloat16* as = As + st * BM * AST;
        __nv_bfloat16* bs = Bs + st * BN * AST;
#pragma unroll
        for (int i = 0; i < 2; i++) {
            int f = tid + i * 256;
            int row = f >> 2, ch = f & 3;
            cp_async16(smem_u32(as + row * AST + ch * 8),
                       A + (long long)(m0 + row) * K + k0 + ch * 8);
        }
#pragma unroll
        for (int i = 0; i < 4; i++) {
            int f = tid + i * 256;
            int row = f >> 2, ch = f & 3;
            cp_async16(smem_u32(bs + row * AST + ch * 8),
                       Bm + (long long)(n0 + row) * K + k0 + ch * 8);
        }
        asm volatile("cp.async.commit_group;");
    };

    // prologue: fill stages 0 and 1
    load_stage(0, 0);
    load_stage(1, BKK);

    for (int c = 0; c < nK; c++) {
        if (c + 1 < nK) asm volatile("cp.async.wait_group 1;");
        else            asm volatile("cp.async.wait_group 0;");
        __syncthreads();

        if (c + 2 < nK) load_stage((c + 2) % MM_STAGES, (long long)(c + 2) * BKK);

        const int buf = c % MM_STAGES;
        const __nv_bfloat16* asb = As + buf * BM * AST;
        const __nv_bfloat16* bsb = Bs + buf * BN * AST;
#pragma unroll
        for (int ks = 0; ks < 2; ks++) {
            uint32_t af[4][4], bfq[4][4];
#pragma unroll
            for (int mt = 0; mt < 4; mt++)
                ldsm_x4(af[mt], smem_u32(asb + (wm + mt * 16 + lr) * AST + ks * 16 + lc));
#pragma unroll
            for (int ng = 0; ng < 4; ng++)
                ldsm_x4(bfq[ng], smem_u32(bsb + (wn + ng * 16 + lr) * AST + ks * 16 + lc));
#pragma unroll
            for (int mt = 0; mt < 4; mt++)
#pragma unroll
                for (int nt = 0; nt < 8; nt++) {
                    const int ng = nt >> 1, sub = nt & 1;
                    mma16816(acc[mt][nt], af[mt], bfq[ng][sub], bfq[ng][sub + 2]);
                }
        }
        __syncthreads();
    }

    // ---- epilogue (fragment layout: lane = 4*g + tg; rows g, g+8; cols 2tg,2tg+1)
    const int g = lane >> 2, tg = lane & 3;
#pragma unroll
    for (int mt = 0; mt < 4; mt++) {
#pragma unroll
        for (int nt = 0; nt < 8; nt++) {
            const int row = m0 + wm + mt * 16 + g;
            const int col = n0 + wn + nt * 8 + 2 * tg;
            const long long o0 = (long long)row * N + col;
            const long long o1 = (long long)(row + 8) * N + col;
            float x0 = acc[mt][nt][0], x1 = acc[mt][nt][1];
            float x2 = acc[mt][nt][2], x3 = acc[mt][nt][3];
            if (EPI == 0) {
                if (BIAS) {
                    float b0 = bias[col], b1 = bias[col + 1];
                    x0 += b0; x1 += b1; x2 += b0; x3 += b1;
                }
                __nv_bfloat16* o = (__nv_bfloat16*)Out + (long long)b * sO;
                *(__nv_bfloat162*)(o + o0) = __floats2bfloat162_rn(x0, x1);
                *(__nv_bfloat162*)(o + o1) = __floats2bfloat162_rn(x2, x3);
            } else {
                float* o = (float*)Out + (long long)b * sO;
                if (EPI == 2) {
                    const float* rs = Res + (long long)b * sO;
                    float2 r0 = *(const float2*)(rs + o0);
                    float2 r1 = *(const float2*)(rs + o1);
                    x0 += r0.x; x1 += r0.y; x2 += r1.x; x3 += r1.y;
                }
                *(float2*)(o + o0) = make_float2(x0, x1);
                *(float2*)(o + o1) = make_float2(x2, x3);
            }
        }
    }
}

// ---------------- elementwise fp32 -> bf16 convert ---------------------------
__global__ __launch_bounds__(256) void cvt_bf16_kernel(const float4* __restrict__ in,
                                                       __nv_bfloat162* __restrict__ out,
                                                       int n4)
{
    int i = blockIdx.x * 256 + threadIdx.x;
    if (i < n4) {
        float4 v = in[i];
        out[2 * i]     = __floats2bfloat162_rn(v.x, v.y);
        out[2 * i + 1] = __floats2bfloat162_rn(v.z, v.w);
    }
}

// ---------------- tiled transpose (R,C) -> (C,R) bf16 ------------------------
template <typename Tin>
__global__ __launch_bounds__(256)
void transpose_bf16_kernel(const Tin* __restrict__ in, __nv_bfloat16* __restrict__ out,
                           int R, int Cc, long long sIn, long long sOut)
{
    __shared__ float t[32][33];
    const int b = blockIdx.z;
    const Tin* I = in + sIn * b;
    __nv_bfloat16* O = out + sOut * b;
    const int c0 = blockIdx.x * 32, r0 = blockIdx.y * 32;
    const int tx = threadIdx.x & 31, ty = threadIdx.x >> 5;
#pragma unroll
    for (int i = 0; i < 32; i += 8)
        t[ty + i][tx] = (float)I[(long long)(r0 + ty + i) * Cc + c0 + tx];
    __syncthreads();
#pragma unroll
    for (int i = 0; i < 32; i += 8)
        O[(long long)(c0 + ty + i) * R + r0 + tx] = __float2bfloat16(t[tx][ty + i]);
}

// ---------------- softmax(lam) -> g_w ---------------------------------------
__global__ void prep_weights_kernel(const float* __restrict__ lam)
{
    if (threadIdx.x == 0) {
        float m = fmaxf(lam[0], fmaxf(lam[1], lam[2]));
        float e0 = __expf(lam[0] - m);
        float e1 = __expf(lam[1] - m);
        float e2 = __expf(lam[2] - m);
        float s = e0 + e1 + e2;
        g_w[0] = e0 / s; g_w[1] = e1 / s; g_w[2] = e2 / s;
    }
}

// ---------------- bias[b,l] = bq . k_txt[b,l,:]  (bf16 k_txt) -----------------
__global__ __launch_bounds__(256) void bias_kernel(const float* __restrict__ bq)
{
    int row = blockIdx.x * 8 + (threadIdx.x >> 5);
    int lane = threadIdx.x & 31;
    const __nv_bfloat16* kr = g_ktxt_bf + (long long)row * C_;
    float s = 0.f;
    for (int c = lane; c < C_; c += 32) s += bq[c] * __bfloat162float(kr[c]);
#pragma unroll
    for (int off = 16; off > 0; off >>= 1) s += __shfl_xor_sync(0xffffffffu, s, off);
    if (lane == 0) g_bias[row] = s;
}

// ---------------- spatial box pooling of logits (k=3 and k=5) ----------------
__global__ __launch_bounds__(256) void pool_kernel()
{
    __shared__ float img[N_];
    const long long base = (long long)blockIdx.x * N_;
    const float* src = g_logits + base;
    for (int i = threadIdx.x; i < N_; i += 256) img[i] = src[i];
    __syncthreads();

    for (int i = threadIdx.x; i < N_; i += 256) {
        int y = i / W_, x = i - y * W_;
        float s3 = 0.f, s5 = 0.f;
#pragma unroll
        for (int dy = -2; dy <= 2; dy++) {
            int yy = y + dy;
            if (yy < 0 || yy >= H_) continue;
#pragma unroll
            for (int dx = -2; dx <= 2; dx++) {
                int xx = x + dx;
                if (xx < 0 || xx >= W_) continue;
                float v = img[yy * W_ + xx];
                s5 += v;
                if (dy >= -1 && dy <= 1 && dx >= -1 && dx <= 1) s3 += v;
            }
        }
        g_pool3[base + i] = s3 * (1.f / 9.f);
        g_pool5[base + i] = s5 * (1.f / 25.f);
    }
}

// ---------------- 3-way softmax over L + weighted combine -> attn^T bf16 -----
#define SM_PAD 17
#define SM_PLANE (L_ * SM_PAD)
__global__ __launch_bounds__(512) void softmax_combine_kernel()
{
    extern __shared__ float sm[];           // 3 * 512 * 17 floats
    __shared__ float coef[NS_][16];

    const int b = blockIdx.y;
    const int n0 = blockIdx.x * 16;
    const int tid = threadIdx.x;
    const float sc = 0.03125f;              // C^{-1/2}

    for (int idx = tid; idx < L_ * 16; idx += 512) {
        int l = idx >> 4, j = idx & 15;
        float bias = g_bias[b * L_ + l];
        long long g = ((long long)(b * L_ + l)) * N_ + n0 + j;
        sm[0 * SM_PLANE + l * SM_PAD + j] = (g_logits[g] + bias) * sc;
        sm[1 * SM_PLANE + l * SM_PAD + j] = (g_pool3[g]  + bias) * sc;
        sm[2 * SM_PLANE + l * SM_PAD + j] = (g_pool5[g]  + bias) * sc;
    }
    __syncthreads();

    const int warp = tid >> 5, lane = tid & 31;
    for (int col = warp; col < NS_ * 16; col += 16) {
        int s = col >> 4, j = col & 15;
        float* base = sm + s * SM_PLANE + j;
        float vals[16];
        float mx = -1e30f;
#pragma unroll
        for (int r = 0; r < 16; r++) {
            vals[r] = base[(lane + r * 32) * SM_PAD];
            mx = fmaxf(mx, vals[r]);
        }
#pragma unroll
        for (int off = 16; off > 0; off >>= 1)
            mx = fmaxf(mx, __shfl_xor_sync(0xffffffffu, mx, off));
        float ssum = 0.f;
#pragma unroll
        for (int r = 0; r < 16; r++) {
            float e = __expf(vals[r] - mx);
            base[(lane + r * 32) * SM_PAD] = e;
            ssum += e;
        }
#pragma unroll
        for (int off = 16; off > 0; off >>= 1)
            ssum += __shfl_xor_sync(0xffffffffu, ssum, off);
        if (lane == 0) coef[s][j] = g_w[s] / ssum;
    }
    __syncthreads();

    // write attn^T (B, N_, L) bf16; one warp per spatial column, coalesced over l
    {
        const int j = warp;                 // 16 warps, one j each
        const float c0 = coef[0][j], c1 = coef[1][j], c2 = coef[2][j];
        __nv_bfloat16* dst = g_attnT_bf + ((long long)(b * N_ + n0 + j)) * L_;
        for (int l = lane; l < L_; l += 32) {
            float v = sm[0 * SM_PLANE + l * SM_PAD + j] * c0
                    + sm[1 * SM_PLANE + l * SM_PAD + j] * c1
                    + sm[2 * SM_PLANE + l * SM_PAD + j] * c2;
            dst[l] = __float2bfloat16(v);
        }
    }
}

// ---------------- t_tok passthrough -----------------------------------------
__global__ __launch_bounds__(256) void copy_kernel(const float4* __restrict__ src,
                                                   float4* __restrict__ dst, int n4)
{
    int i = blockIdx.x * 256 + threadIdx.x;
    if (i < n4) dst[i] = src[i];
}

// ---------------- host ------------------------------------------------------
extern "C" void kernel_launch(void* const* d_in, const int* in_sizes, int n_in,
                              void* d_out, int out_size)
{
    const float* v_feat = (const float*)d_in[0];   // (B,C,H,W)
    const float* t_tok  = (const float*)d_in[1];   // (B,L,Ct)
    const float* Wq     = (const float*)d_in[2];   // (C,C)
    const float* bq     = (const float*)d_in[3];
    const float* Wk     = (const float*)d_in[4];   // (Ct,C)
    const float* bk     = (const float*)d_in[5];
    const float* Wv     = (const float*)d_in[6];   // (Ct,C)
    const float* bv     = (const float*)d_in[7];
    const float* lam    = (const float*)d_in[8];   // (3,)
    float* out = (float*)d_out;

    __nv_bfloat16 *p_ttok, *p_WkT, *p_WvT, *p_Wq, *p_ktxt, *p_vtxt, *p_vtxtT,
                  *p_vflat, *p_kq, *p_attnT;
    float *p_logits;
    cudaGetSymbolAddress((void**)&p_ttok,  g_ttok_bf);
    cudaGetSymbolAddress((void**)&p_WkT,   g_WkT);
    cudaGetSymbolAddress((void**)&p_WvT,   g_WvT);
    cudaGetSymbolAddress((void**)&p_Wq,    g_Wq_bf);
    cudaGetSymbolAddress((void**)&p_ktxt,  g_ktxt_bf);
    cudaGetSymbolAddress((void**)&p_vtxt,  g_vtxt_bf);
    cudaGetSymbolAddress((void**)&p_vtxtT, g_vtxtT_bf);
    cudaGetSymbolAddress((void**)&p_vflat, g_vflat_bf);
    cudaGetSymbolAddress((void**)&p_kq,    g_kq_bf);
    cudaGetSymbolAddress((void**)&p_attnT, g_attnT_bf);
    cudaGetSymbolAddress((void**)&p_logits, g_logits);

    cudaFuncSetAttribute(mm_bf16<0, true>,  cudaFuncAttributeMaxDynamicSharedMemorySize, MM_SMEM);
    cudaFuncSetAttribute(mm_bf16<0, false>, cudaFuncAttributeMaxDynamicSharedMemorySize, MM_SMEM);
    cudaFuncSetAttribute(mm_bf16<1, false>, cudaFuncAttributeMaxDynamicSharedMemorySize, MM_SMEM);
    cudaFuncSetAttribute(mm_bf16<2, false>, cudaFuncAttributeMaxDynamicSharedMemorySize, MM_SMEM);

    prep_weights_kernel<<<1, 32>>>(lam);

    // convert t_tok and Wq -> bf16 (Wq keeps original (Cin,Cout) layout)
    {
        int n4 = (B_ * L_ * CT_) / 4;
        cvt_bf16_kernel<<<(n4 + 255) / 256, 256>>>((const float4*)t_tok,
                                                   (__nv_bfloat162*)p_ttok, n4);
        int w4 = (C_ * C_) / 4;
        cvt_bf16_kernel<<<(w4 + 255) / 256, 256>>>((const float4*)Wq,
                                                   (__nv_bfloat162*)p_Wq, w4);
    }
    // transpose K/V weights -> bf16 (Cout, Cin)
    transpose_bf16_kernel<float><<<dim3(C_ / 32, CT_ / 32, 1), 256>>>(Wk, p_WkT, CT_, C_, 0, 0);
    transpose_bf16_kernel<float><<<dim3(C_ / 32, CT_ / 32, 1), 256>>>(Wv, p_WvT, CT_, C_, 0, 0);
    // v_feat (B,C,N) -> v_flat (B,N,C) bf16
    transpose_bf16_kernel<float><<<dim3(N_ / 32, C_ / 32, B_), 256>>>(
        v_feat, p_vflat, C_, N_, (long long)C_ * N_, (long long)N_ * C_);

    // k_txt = t_tok @ Wk + bk  -> bf16 (B*L, C)
    mm_bf16<0, true><<<dim3(C_ / BN, (B_ * L_) / BM, 1), 256, MM_SMEM>>>(
        p_ttok, p_WkT, p_ktxt, bk, nullptr, C_, CT_, 0, 0, 0);
    // v_txt = t_tok @ Wv + bv  -> bf16 (B*L, C)
    mm_bf16<0, true><<<dim3(C_ / BN, (B_ * L_) / BM, 1), 256, MM_SMEM>>>(
        p_ttok, p_WvT, p_vtxt, bv, nullptr, C_, CT_, 0, 0, 0);

    bias_kernel<<<(B_ * L_) / 8, 256>>>(bq);

    // v_txt (B,L,C) -> v_txt^T (B,C,L) bf16
    transpose_bf16_kernel<__nv_bfloat16><<<dim3(C_ / 32, L_ / 32, B_), 256>>>(
        p_vtxt, p_vtxtT, L_, C_, (long long)L_ * C_, (long long)C_ * L_);

    // kq = k_txt @ Wq^T  -> bf16 (B*L, C).  Bop[n=cin, k=cout] = Wq[cin,cout]
    mm_bf16<0, false><<<dim3(C_ / BN, (B_ * L_) / BM, 1), 256, MM_SMEM>>>(
        p_ktxt, p_Wq, p_kq, nullptr, nullptr, C_, C_, 0, 0, 0);

    // logits[b] = kq[b] @ v_flat[b]^T  -> fp32 (B,L,N)
    mm_bf16<1, false><<<dim3(N_ / BN, L_ / BM, B_), 256, MM_SMEM>>>(
        p_kq, p_vflat, p_logits, nullptr, nullptr, N_, C_,
        (long long)L_ * C_, (long long)N_ * C_, (long long)L_ * N_);

    pool_kernel<<<B_ * L_, 256>>>();

    size_t smem = (size_t)NS_ * SM_PLANE * sizeof(float);
    cudaFuncSetAttribute(softmax_combine_kernel,
                         cudaFuncAttributeMaxDynamicSharedMemorySize, (int)smem);
    softmax_combine_kernel<<<dim3(N_ / 16, B_), 512, smem>>>();

    // out_vis[b] = v_txt[b]^T @ attn[b] + v_feat[b]  -> fp32 (B,C,N)
    mm_bf16<2, false><<<dim3(N_ / BN, C_ / BM, B_), 256, MM_SMEM>>>(
        p_vtxtT, p_attnT, out, nullptr, v_feat, N_, L_,
        (long long)C_ * L_, (long long)N_ * L_, (long long)C_ * N_);

    // t_tok passthrough
    int n4 = (B_ * L_ * CT_) / 4;
    copy_kernel<<<(n4 + 255) / 256, 256>>>(
        (const float4*)t_tok, (float4*)(out + (size_t)B_ * C_ * N_), n4);
}

// round 12
// speedup vs baseline: 4.9993x; 1.0442x over previous
#include <cuda_runtime.h>
#include <cuda_bf16.h>
#include <cstdint>
#include <math.h>

// Shapes (fixed by the problem)
#define B_  16
#define C_  1024
#define H_  48
#define W_  48
#define N_  2304   // H*W
#define L_  512
#define CT_ 768
#define NS_ 3

// ---------------- scratch (device globals; no allocation allowed) ----------
__device__ __nv_bfloat16 g_ttok_bf[B_ * L_ * CT_];     // (B,L,Ct)
__device__ __nv_bfloat16 g_Wq_bf[C_ * C_];             // (Cin,Cout) original
__device__ __nv_bfloat16 g_Wk_bf[CT_ * C_];            // (Ct,C) original
__device__ __nv_bfloat16 g_WvT[C_ * CT_];              // (C,Ct)
__device__ __nv_bfloat16 g_WkqT[C_ * CT_];             // (C,Ct)  Wq . Wk^T
__device__ __nv_bfloat16 g_vtxtT_bf[B_ * C_ * L_];     // (B,C,L) v_txt^T (+bv)
__device__ __nv_bfloat16 g_vflat_bf[B_ * N_ * C_];     // (B,N,C)
__device__ __nv_bfloat16 g_kq_bf[B_ * L_ * C_];        // (B,L,C)
__device__ __nv_bfloat16 g_attnT_bf[B_ * N_ * L_];     // (B,N,L) combined attn^T
__device__ __nv_bfloat16 g_pool3[B_ * L_ * N_];        // (B,L,N) bf16
__device__ __nv_bfloat16 g_pool5[B_ * L_ * N_];        // (B,L,N) bf16
__device__ float g_logits[B_ * L_ * N_];               // (B,L,N) fp32
__device__ float g_bias[B_ * L_];                      // bq . k_txt[b,l]
__device__ float g_wkbq[CT_];                          // Wk @ bq
__device__ float g_bkq[C_];                            // Wq @ bk  (per cin)
__device__ float g_w[NS_];                             // softmax(lam)
__device__ float g_bqbk;                               // bq . bk

// ======================= helpers ============================================
__device__ __forceinline__ uint32_t smem_u32(const void* p) {
    uint32_t a;
    asm("{ .reg .u64 t; cvta.to.shared.u64 t, %1; cvt.u32.u64 %0, t; }"
        : "=r"(a) : "l"(p));
    return a;
}
__device__ __forceinline__ void ldsm_x4(uint32_t* f, uint32_t addr) {
    asm volatile("ldmatrix.sync.aligned.m8n8.x4.shared.b16 {%0,%1,%2,%3}, [%4];"
                 : "=r"(f[0]), "=r"(f[1]), "=r"(f[2]), "=r"(f[3]) : "r"(addr));
}
__device__ __forceinline__ void mma16816(float* d, const uint32_t* a,
                                         uint32_t b0, uint32_t b1) {
    asm volatile("mma.sync.aligned.m16n8k16.row.col.f32.bf16.bf16.f32 "
                 "{%0,%1,%2,%3}, {%4,%5,%6,%7}, {%8,%9}, {%0,%1,%2,%3};"
                 : "+f"(d[0]), "+f"(d[1]), "+f"(d[2]), "+f"(d[3])
                 : "r"(a[0]), "r"(a[1]), "r"(a[2]), "r"(a[3]), "r"(b0), "r"(b1));
}
__device__ __forceinline__ void cp_async16(uint32_t dst, const void* src) {
    asm volatile("cp.async.cg.shared.global [%0], [%1], 16;" :: "r"(dst), "l"(src));
}

// ======================= HMMA bf16 batched GEMM =============================
// C[m,n] = sum_k A[m,k] * Bop[n,k]; A (M,K) bf16 K-major, Bop (N,K) bf16 K-major.
// CTA tile 128x256x32, 3-stage cp.async pipeline, 256 threads
// (8 warps, 2x4 grid of 64x64 warp tiles).
// EPI: 0 = bf16 out, 1 = fp32 out, 2 = fp32 out + Res add.
// BMODE: 0 = none, 1 = +bias[n] (column), 2 = +bias[m] (row).
#define BM 128
#define BN 256
#define BKK 32
#define AST 40   // bf16 elems per smem row (32 + 8 pad) => 80B stride
#define MM_STAGES 3
#define MM_SMEM (MM_STAGES * (BM + BN) * AST * 2)   // 92160 bytes

template <int EPI, int BMODE>
__global__ __launch_bounds__(256)
void mm_bf16(const __nv_bfloat16* __restrict__ A, const __nv_bfloat16* __restrict__ Bm,
             void* __restrict__ Out, const float* __restrict__ bias,
             const float* __restrict__ Res,
             int N, int K, long long sA, long long sB, long long sO)
{
    extern __shared__ __nv_bfloat16 dsm[];
    __nv_bfloat16* As = dsm;                        // [3][BM*AST]
    __nv_bfloat16* Bs = dsm + MM_STAGES * BM * AST; // [3][BN*AST]

    const int b = blockIdx.z;
    A  += sA * b;
    Bm += sB * b;
    const int m0 = blockIdx.y * BM;
    const int n0 = blockIdx.x * BN;
    const int tid = threadIdx.x, wid = tid >> 5, lane = tid & 31;
    const int wm = (wid & 1) * 64;    // warp m offset within tile
    const int wn = (wid >> 1) * 64;   // warp n offset within tile

    float acc[4][8][4];
#pragma unroll
    for (int i = 0; i < 4; i++)
#pragma unroll
        for (int j = 0; j < 8; j++)
#pragma unroll
            for (int r = 0; r < 4; r++) acc[i][j][r] = 0.f;

    const int nK = K / BKK;
    const int lr = lane & 15;
    const int lc = (lane >> 4) * 8;

    auto load_stage = [&](int st, long long k0) {
        __nv_bfloat16* as = As + st * BM * AST;
        __nv_bfloat16* bs = Bs + st * BN * AST;
#pragma unroll
        for (int i = 0; i < 2; i++) {
            int f = tid + i * 256;
            int row = f >> 2, ch = f & 3;
            cp_async16(smem_u32(as + row * AST + ch * 8),
                       A + (long long)(m0 + row) * K + k0 + ch * 8);
        }
#pragma unroll
        for (int i = 0; i < 4; i++) {
            int f = tid + i * 256;
            int row = f >> 2, ch = f & 3;
            cp_async16(smem_u32(bs + row * AST + ch * 8),
                       Bm + (long long)(n0 + row) * K + k0 + ch * 8);
        }
        asm volatile("cp.async.commit_group;");
    };

    load_stage(0, 0);
    load_stage(1, BKK);

    for (int c = 0; c < nK; c++) {
        if (c + 1 < nK) asm volatile("cp.async.wait_group 1;");
        else            asm volatile("cp.async.wait_group 0;");
        __syncthreads();

        if (c + 2 < nK) load_stage((c + 2) % MM_STAGES, (long long)(c + 2) * BKK);

        const int buf = c % MM_STAGES;
        const __nv_bfloat16* asb = As + buf * BM * AST;
        const __nv_bfloat16* bsb = Bs + buf * BN * AST;
#pragma unroll
        for (int ks = 0; ks < 2; ks++) {
            uint32_t af[4][4], bfq[4][4];
#pragma unroll
            for (int mt = 0; mt < 4; mt++)
                ldsm_x4(af[mt], smem_u32(asb + (wm + mt * 16 + lr) * AST + ks * 16 + lc));
#pragma unroll
            for (int ng = 0; ng < 4; ng++)
                ldsm_x4(bfq[ng], smem_u32(bsb + (wn + ng * 16 + lr) * AST + ks * 16 + lc));
#pragma unroll
            for (int mt = 0; mt < 4; mt++)
#pragma unroll
                for (int nt = 0; nt < 8; nt++) {
                    const int ng = nt >> 1, sub = nt & 1;
                    mma16816(acc[mt][nt], af[mt], bfq[ng][sub], bfq[ng][sub + 2]);
                }
        }
        __syncthreads();
    }

    // ---- epilogue (fragment layout: lane = 4*g + tg; rows g, g+8; cols 2tg,2tg+1)
    const int g = lane >> 2, tg = lane & 3;
#pragma unroll
    for (int mt = 0; mt < 4; mt++) {
#pragma unroll
        for (int nt = 0; nt < 8; nt++) {
            const int row = m0 + wm + mt * 16 + g;
            const int col = n0 + wn + nt * 8 + 2 * tg;
            const long long o0 = (long long)row * N + col;
            const long long o1 = (long long)(row + 8) * N + col;
            float x0 = acc[mt][nt][0], x1 = acc[mt][nt][1];
            float x2 = acc[mt][nt][2], x3 = acc[mt][nt][3];
            if (BMODE == 1) {
                float b0 = bias[col], b1 = bias[col + 1];
                x0 += b0; x1 += b1; x2 += b0; x3 += b1;
            } else if (BMODE == 2) {
                float b0 = bias[row], b1 = bias[row + 8];
                x0 += b0; x1 += b0; x2 += b1; x3 += b1;
            }
            if (EPI == 0) {
                __nv_bfloat16* o = (__nv_bfloat16*)Out + (long long)b * sO;
                *(__nv_bfloat162*)(o + o0) = __floats2bfloat162_rn(x0, x1);
                *(__nv_bfloat162*)(o + o1) = __floats2bfloat162_rn(x2, x3);
            } else {
                float* o = (float*)Out + (long long)b * sO;
                if (EPI == 2) {
                    const float* rs = Res + (long long)b * sO;
                    float2 r0 = *(const float2*)(rs + o0);
                    float2 r1 = *(const float2*)(rs + o1);
                    x0 += r0.x; x1 += r0.y; x2 += r1.x; x3 += r1.y;
                }
                *(float2*)(o + o0) = make_float2(x0, x1);
                *(float2*)(o + o1) = make_float2(x2, x3);
            }
        }
    }
}

// ---------------- elementwise fp32 -> bf16 convert ---------------------------
__global__ __launch_bounds__(256) void cvt_bf16_kernel(const float4* __restrict__ in,
                                                       __nv_bfloat162* __restrict__ out,
                                                       int n4)
{
    int i = blockIdx.x * 256 + threadIdx.x;
    if (i < n4) {
        float4 v = in[i];
        out[2 * i]     = __floats2bfloat162_rn(v.x, v.y);
        out[2 * i + 1] = __floats2bfloat162_rn(v.z, v.w);
    }
}

// ---------------- tiled transpose (R,C) -> (C,R) bf16 ------------------------
__global__ __launch_bounds__(256)
void transpose_bf16_kernel(const float* __restrict__ in, __nv_bfloat16* __restrict__ out,
                           int R, int Cc, long long sIn, long long sOut)
{
    __shared__ float t[32][33];
    const int b = blockIdx.z;
    const float* I = in + sIn * b;
    __nv_bfloat16* O = out + sOut * b;
    const int c0 = blockIdx.x * 32, r0 = blockIdx.y * 32;
    const int tx = threadIdx.x & 31, ty = threadIdx.x >> 5;
#pragma unroll
    for (int i = 0; i < 32; i += 8)
        t[ty + i][tx] = I[(long long)(r0 + ty + i) * Cc + c0 + tx];
    __syncthreads();
#pragma unroll
    for (int i = 0; i < 32; i += 8)
        O[(long long)(c0 + ty + i) * R + r0 + tx] = __float2bfloat16(t[tx][ty + i]);
}

// ---------------- softmax(lam) -> g_w ; bqbk = bq.bk -------------------------
__global__ void prep_weights_kernel(const float* __restrict__ lam,
                                    const float* __restrict__ bq,
                                    const float* __restrict__ bk)
{
    const int lane = threadIdx.x;
    float s = 0.f;
    for (int c = lane; c < C_; c += 32) s += bq[c] * bk[c];
#pragma unroll
    for (int off = 16; off > 0; off >>= 1) s += __shfl_xor_sync(0xffffffffu, s, off);
    if (lane == 0) {
        g_bqbk = s;
        float m = fmaxf(lam[0], fmaxf(lam[1], lam[2]));
        float e0 = __expf(lam[0] - m);
        float e1 = __expf(lam[1] - m);
        float e2 = __expf(lam[2] - m);
        float t = e0 + e1 + e2;
        g_w[0] = e0 / t; g_w[1] = e1 / t; g_w[2] = e2 / t;
    }
}

// ---------------- out[r] = M[r,:] . v   (fp32, warp per row) -----------------
__global__ __launch_bounds__(256)
void dotrows_kernel(const float* __restrict__ M, const float* __restrict__ v,
                    float* __restrict__ out, int cols)
{
    int row = blockIdx.x * 8 + (threadIdx.x >> 5);
    int lane = threadIdx.x & 31;
    const float* mr = M + (long long)row * cols;
    float s = 0.f;
    for (int c = lane; c < cols; c += 32) s += mr[c] * v[c];
#pragma unroll
    for (int off = 16; off > 0; off >>= 1) s += __shfl_xor_sync(0xffffffffu, s, off);
    if (lane == 0) out[row] = s;
}

// ---------------- bias[b,l] = t_tok[b,l,:] . wkbq + bqbk ---------------------
__global__ __launch_bounds__(256) void bias_kernel(const float* __restrict__ t_tok)
{
    int row = blockIdx.x * 8 + (threadIdx.x >> 5);   // 0 .. B*L-1
    int lane = threadIdx.x & 31;
    const float* tr = t_tok + (long long)row * CT_;
    float s = 0.f;
    for (int c = lane; c < CT_; c += 32) s += tr[c] * g_wkbq[c];
#pragma unroll
    for (int off = 16; off > 0; off >>= 1) s += __shfl_xor_sync(0xffffffffu, s, off);
    if (lane == 0) g_bias[row] = s + g_bqbk;
}

// ---------------- spatial box pooling of logits (k=3 and k=5) -> bf16 --------
__global__ __launch_bounds__(256) void pool_kernel()
{
    __shared__ float img[N_];
    const long long base = (long long)blockIdx.x * N_;
    const float* src = g_logits + base;
    for (int i = threadIdx.x; i < N_; i += 256) img[i] = src[i];
    __syncthreads();

    for (int i = threadIdx.x; i < N_; i += 256) {
        int y = i / W_, x = i - y * W_;
        float s3 = 0.f, s5 = 0.f;
#pragma unroll
        for (int dy = -2; dy <= 2; dy++) {
            int yy = y + dy;
            if (yy < 0 || yy >= H_) continue;
#pragma unroll
            for (int dx = -2; dx <= 2; dx++) {
                int xx = x + dx;
                if (xx < 0 || xx >= W_) continue;
                float v = img[yy * W_ + xx];
                s5 += v;
                if (dy >= -1 && dy <= 1 && dx >= -1 && dx <= 1) s3 += v;
            }
        }
        g_pool3[base + i] = __float2bfloat16(s3 * (1.f / 9.f));
        g_pool5[base + i] = __float2bfloat16(s5 * (1.f / 25.f));
    }
}

// ---------------- 3-way softmax over L + weighted combine -> attn^T bf16 -----
#define SM_PAD 17
#define SM_PLANE (L_ * SM_PAD)
__global__ __launch_bounds__(512) void softmax_combine_kernel()
{
    extern __shared__ float sm[];           // 3 * 512 * 17 floats
    __shared__ float coef[NS_][16];

    const int b = blockIdx.y;
    const int n0 = blockIdx.x * 16;
    const int tid = threadIdx.x;
    const float sc = 0.03125f;              // C^{-1/2}

    for (int idx = tid; idx < L_ * 16; idx += 512) {
        int l = idx >> 4, j = idx & 15;
        float bias = g_bias[b * L_ + l];
        long long g = ((long long)(b * L_ + l)) * N_ + n0 + j;
        sm[0 * SM_PLANE + l * SM_PAD + j] = (g_logits[g] + bias) * sc;
        sm[1 * SM_PLANE + l * SM_PAD + j] = (__bfloat162float(g_pool3[g]) + bias) * sc;
        sm[2 * SM_PLANE + l * SM_PAD + j] = (__bfloat162float(g_pool5[g]) + bias) * sc;
    }
    __syncthreads();

    const int warp = tid >> 5, lane = tid & 31;
    for (int col = warp; col < NS_ * 16; col += 16) {
        int s = col >> 4, j = col & 15;
        float* base = sm + s * SM_PLANE + j;
        float vals[16];
        float mx = -1e30f;
#pragma unroll
        for (int r = 0; r < 16; r++) {
            vals[r] = base[(lane + r * 32) * SM_PAD];
            mx = fmaxf(mx, vals[r]);
        }
#pragma unroll
        for (int off = 16; off > 0; off >>= 1)
            mx = fmaxf(mx, __shfl_xor_sync(0xffffffffu, mx, off));
        float ssum = 0.f;
#pragma unroll
        for (int r = 0; r < 16; r++) {
            float e = __expf(vals[r] - mx);
            base[(lane + r * 32) * SM_PAD] = e;
            ssum += e;
        }
#pragma unroll
        for (int off = 16; off > 0; off >>= 1)
            ssum += __shfl_xor_sync(0xffffffffu, ssum, off);
        if (lane == 0) coef[s][j] = g_w[s] / ssum;
    }
    __syncthreads();

    // write attn^T (B, N_, L) bf16; one warp per spatial column, coalesced over l
    {
        const int j = warp;                 // 16 warps, one j each
        const float c0 = coef[0][j], c1 = coef[1][j], c2 = coef[2][j];
        __nv_bfloat16* dst = g_attnT_bf + ((long long)(b * N_ + n0 + j)) * L_;
        for (int l = lane; l < L_; l += 32) {
            float v = sm[0 * SM_PLANE + l * SM_PAD + j] * c0
                    + sm[1 * SM_PLANE + l * SM_PAD + j] * c1
                    + sm[2 * SM_PLANE + l * SM_PAD + j] * c2;
            dst[l] = __float2bfloat16(v);
        }
    }
}

// ---------------- t_tok passthrough -----------------------------------------
__global__ __launch_bounds__(256) void copy_kernel(const float4* __restrict__ src,
                                                   float4* __restrict__ dst, int n4)
{
    int i = blockIdx.x * 256 + threadIdx.x;
    if (i < n4) dst[i] = src[i];
}

// ---------------- host ------------------------------------------------------
extern "C" void kernel_launch(void* const* d_in, const int* in_sizes, int n_in,
                              void* d_out, int out_size)
{
    const float* v_feat = (const float*)d_in[0];   // (B,C,H,W)
    const float* t_tok  = (const float*)d_in[1];   // (B,L,Ct)
    const float* Wq     = (const float*)d_in[2];   // (C,C)
    const float* bq     = (const float*)d_in[3];
    const float* Wk     = (const float*)d_in[4];   // (Ct,C)
    const float* bk     = (const float*)d_in[5];
    const float* Wv     = (const float*)d_in[6];   // (Ct,C)
    const float* bv     = (const float*)d_in[7];
    const float* lam    = (const float*)d_in[8];   // (3,)
    float* out = (float*)d_out;

    __nv_bfloat16 *p_ttok, *p_Wq, *p_Wk, *p_WvT, *p_WkqT, *p_vtxtT, *p_vflat,
                  *p_kq, *p_attnT;
    float *p_logits, *p_wkbq, *p_bkq;
    cudaGetSymbolAddress((void**)&p_ttok,  g_ttok_bf);
    cudaGetSymbolAddress((void**)&p_Wq,    g_Wq_bf);
    cudaGetSymbolAddress((void**)&p_Wk,    g_Wk_bf);
    cudaGetSymbolAddress((void**)&p_WvT,   g_WvT);
    cudaGetSymbolAddress((void**)&p_WkqT,  g_WkqT);
    cudaGetSymbolAddress((void**)&p_vtxtT, g_vtxtT_bf);
    cudaGetSymbolAddress((void**)&p_vflat, g_vflat_bf);
    cudaGetSymbolAddress((void**)&p_kq,    g_kq_bf);
    cudaGetSymbolAddress((void**)&p_attnT, g_attnT_bf);
    cudaGetSymbolAddress((void**)&p_logits, g_logits);
    cudaGetSymbolAddress((void**)&p_wkbq,  g_wkbq);
    cudaGetSymbolAddress((void**)&p_bkq,   g_bkq);

    cudaFuncSetAttribute(mm_bf16<0, 0>, cudaFuncAttributeMaxDynamicSharedMemorySize, MM_SMEM);
    cudaFuncSetAttribute(mm_bf16<0, 1>, cudaFuncAttributeMaxDynamicSharedMemorySize, MM_SMEM);
    cudaFuncSetAttribute(mm_bf16<0, 2>, cudaFuncAttributeMaxDynamicSharedMemorySize, MM_SMEM);
    cudaFuncSetAttribute(mm_bf16<1, 0>, cudaFuncAttributeMaxDynamicSharedMemorySize, MM_SMEM);
    cudaFuncSetAttribute(mm_bf16<2, 0>, cudaFuncAttributeMaxDynamicSharedMemorySize, MM_SMEM);

    prep_weights_kernel<<<1, 32>>>(lam, bq, bk);

    // bf16 conversions (original layouts)
    {
        int n4 = (B_ * L_ * CT_) / 4;
        cvt_bf16_kernel<<<(n4 + 255) / 256, 256>>>((const float4*)t_tok,
                                                   (__nv_bfloat162*)p_ttok, n4);
        int w4 = (C_ * C_) / 4;
        cvt_bf16_kernel<<<(w4 + 255) / 256, 256>>>((const float4*)Wq,
                                                   (__nv_bfloat162*)p_Wq, w4);
        int k4 = (CT_ * C_) / 4;
        cvt_bf16_kernel<<<(k4 + 255) / 256, 256>>>((const float4*)Wk,
                                                   (__nv_bfloat162*)p_Wk, k4);
    }
    // Wv -> WvT bf16 (C, Ct)
    transpose_bf16_kernel<<<dim3(C_ / 32, CT_ / 32, 1), 256>>>(Wv, p_WvT, CT_, C_, 0, 0);
    // v_feat (B,C,N) -> v_flat (B,N,C) bf16
    transpose_bf16_kernel<<<dim3(N_ / 32, C_ / 32, B_), 256>>>(
        v_feat, p_vflat, C_, N_, (long long)C_ * N_, (long long)N_ * C_);

    // vector precomputes (exact fp32)
    dotrows_kernel<<<CT_ / 8, 256>>>(Wk, bq, p_wkbq, C_);   // wkbq[ct] = Wk[ct,:].bq
    dotrows_kernel<<<C_ / 8, 256>>>(Wq, bk, p_bkq, C_);     // bkq[cin] = Wq[cin,:].bk
    bias_kernel<<<(B_ * L_) / 8, 256>>>(t_tok);             // bias = t_tok.wkbq + bq.bk

    // WkqT[cin, ct] = sum_cout Wq[cin,cout] * Wk[ct,cout]   (M=C, N=Ct, K=C)
    mm_bf16<0, 0><<<dim3(CT_ / BN, C_ / BM, 1), 256, MM_SMEM>>>(
        p_Wq, p_Wk, p_WkqT, nullptr, nullptr, CT_, C_, 0, 0, 0);

    // kq = t_tok @ WkqT^T + bkq  -> bf16 (B*L, C)   (M=B*L, N=C, K=Ct)
    mm_bf16<0, 1><<<dim3(C_ / BN, (B_ * L_) / BM, 1), 256, MM_SMEM>>>(
        p_ttok, p_WkqT, p_kq, p_bkq, nullptr, C_, CT_, 0, 0, 0);

    // vtxtT[b] = WvT @ t_tok[b]^T + bv (row bias) -> bf16 (B,C,L)  (M=C,N=L,K=Ct)
    mm_bf16<0, 2><<<dim3(L_ / BN, C_ / BM, B_), 256, MM_SMEM>>>(
        p_WvT, p_ttok, p_vtxtT, bv, nullptr, L_, CT_,
        0, (long long)L_ * CT_, (long long)C_ * L_);

    // logits[b] = kq[b] @ v_flat[b]^T  -> fp32 (B,L,N)
    mm_bf16<1, 0><<<dim3(N_ / BN, L_ / BM, B_), 256, MM_SMEM>>>(
        p_kq, p_vflat, p_logits, nullptr, nullptr, N_, C_,
        (long long)L_ * C_, (long long)N_ * C_, (long long)L_ * N_);

    pool_kernel<<<B_ * L_, 256>>>();

    size_t smem = (size_t)NS_ * SM_PLANE * sizeof(float);
    cudaFuncSetAttribute(softmax_combine_kernel,
                         cudaFuncAttributeMaxDynamicSharedMemorySize, (int)smem);
    softmax_combine_kernel<<<dim3(N_ / 16, B_), 512, smem>>>();

    // out_vis[b] = v_txt[b]^T @ attn[b] + v_feat[b]  -> fp32 (B,C,N)
    mm_bf16<2, 0><<<dim3(N_ / BN, C_ / BM, B_), 256, MM_SMEM>>>(
        p_vtxtT, p_attnT, out, nullptr, v_feat, N_, L_,
        (long long)C_ * L_, (long long)N_ * L_, (long long)C_ * N_);

    // t_tok passthrough
    int n4 = (B_ * L_ * CT_) / 4;
    copy_kernel<<<(n4 + 255) / 256, 256>>>(
        (const float4*)t_tok, (float4*)(out + (size_t)B_ * C_ * N_), n4);
}

// round 13
// speedup vs baseline: 5.0826x; 1.0167x over previous
#include <cuda_runtime.h>
#include <cuda_bf16.h>
#include <cstdint>
#include <math.h>

// Shapes (fixed by the problem)
#define B_  16
#define C_  1024
#define H_  48
#define W_  48
#define N_  2304   // H*W
#define L_  512
#define CT_ 768
#define NS_ 3

// ---------------- scratch (device globals; no allocation allowed) ----------
__device__ __nv_bfloat16 g_ttok_bf[B_ * L_ * CT_];     // (B,L,Ct)
__device__ __nv_bfloat16 g_Wq_bf[C_ * C_];             // (Cin,Cout) original
__device__ __nv_bfloat16 g_Wk_bf[CT_ * C_];            // (Ct,C) original
__device__ __nv_bfloat16 g_WvT[C_ * CT_];              // (C,Ct)
__device__ __nv_bfloat16 g_WkqT[C_ * CT_];             // (C,Ct)  Wq . Wk^T
__device__ __nv_bfloat16 g_vtxtT_bf[B_ * C_ * L_];     // (B,C,L) v_txt^T (+bv)
__device__ __nv_bfloat16 g_vflat_bf[B_ * N_ * C_];     // (B,N,C)
__device__ __nv_bfloat16 g_kq_bf[B_ * L_ * C_];        // (B,L,C)
__device__ __nv_bfloat16 g_attnT_bf[B_ * N_ * L_];     // (B,N,L) combined attn^T
__device__ __nv_bfloat16 g_logits_bf[B_ * L_ * N_];    // (B,L,N) bf16
__device__ float g_bias[B_ * L_];                      // bq . k_txt[b,l]
__device__ float g_wkbq[CT_];                          // Wk @ bq
__device__ float g_bkq[C_];                            // Wq @ bk  (per cin)
__device__ float g_w[NS_];                             // softmax(lam)
__device__ float g_bqbk;                               // bq . bk

// ======================= helpers ============================================
__device__ __forceinline__ uint32_t smem_u32(const void* p) {
    uint32_t a;
    asm("{ .reg .u64 t; cvta.to.shared.u64 t, %1; cvt.u32.u64 %0, t; }"
        : "=r"(a) : "l"(p));
    return a;
}
__device__ __forceinline__ void ldsm_x4(uint32_t* f, uint32_t addr) {
    asm volatile("ldmatrix.sync.aligned.m8n8.x4.shared.b16 {%0,%1,%2,%3}, [%4];"
                 : "=r"(f[0]), "=r"(f[1]), "=r"(f[2]), "=r"(f[3]) : "r"(addr));
}
__device__ __forceinline__ void mma16816(float* d, const uint32_t* a,
                                         uint32_t b0, uint32_t b1) {
    asm volatile("mma.sync.aligned.m16n8k16.row.col.f32.bf16.bf16.f32 "
                 "{%0,%1,%2,%3}, {%4,%5,%6,%7}, {%8,%9}, {%0,%1,%2,%3};"
                 : "+f"(d[0]), "+f"(d[1]), "+f"(d[2]), "+f"(d[3])
                 : "r"(a[0]), "r"(a[1]), "r"(a[2]), "r"(a[3]), "r"(b0), "r"(b1));
}
__device__ __forceinline__ void cp_async16(uint32_t dst, const void* src) {
    asm volatile("cp.async.cg.shared.global [%0], [%1], 16;" :: "r"(dst), "l"(src));
}

// ======================= HMMA bf16 batched GEMM =============================
// C[m,n] = sum_k A[m,k] * Bop[n,k]; A (M,K) bf16 K-major, Bop (N,K) bf16 K-major.
// CTA tile 128x256x32, 3-stage cp.async pipeline, 256 threads
// (8 warps, 2x4 grid of 64x64 warp tiles).
// EPI: 0 = bf16 out, 1 = fp32 out, 2 = fp32 out + Res add.
// BMODE: 0 = none, 1 = +bias[n] (column), 2 = +bias[m] (row).
#define BM 128
#define BN 256
#define BKK 32
#define AST 40   // bf16 elems per smem row (32 + 8 pad) => 80B stride
#define MM_STAGES 3
#define MM_SMEM (MM_STAGES * (BM + BN) * AST * 2)   // 92160 bytes

template <int EPI, int BMODE>
__global__ __launch_bounds__(256)
void mm_bf16(const __nv_bfloat16* __restrict__ A, const __nv_bfloat16* __restrict__ Bm,
             void* __restrict__ Out, const float* __restrict__ bias,
             const float* __restrict__ Res,
             int N, int K, long long sA, long long sB, long long sO)
{
    extern __shared__ __nv_bfloat16 dsm[];
    __nv_bfloat16* As = dsm;                        // [3][BM*AST]
    __nv_bfloat16* Bs = dsm + MM_STAGES * BM * AST; // [3][BN*AST]

    const int b = blockIdx.z;
    A  += sA * b;
    Bm += sB * b;
    const int m0 = blockIdx.y * BM;
    const int n0 = blockIdx.x * BN;
    const int tid = threadIdx.x, wid = tid >> 5, lane = tid & 31;
    const int wm = (wid & 1) * 64;    // warp m offset within tile
    const int wn = (wid >> 1) * 64;   // warp n offset within tile

    float acc[4][8][4];
#pragma unroll
    for (int i = 0; i < 4; i++)
#pragma unroll
        for (int j = 0; j < 8; j++)
#pragma unroll
            for (int r = 0; r < 4; r++) acc[i][j][r] = 0.f;

    const int nK = K / BKK;
    const int lr = lane & 15;
    const int lc = (lane >> 4) * 8;

    auto load_stage = [&](int st, long long k0) {
        __nv_bfloat16* as = As + st * BM * AST;
        __nv_bfloat16* bs = Bs + st * BN * AST;
#pragma unroll
        for (int i = 0; i < 2; i++) {
            int f = tid + i * 256;
            int row = f >> 2, ch = f & 3;
            cp_async16(smem_u32(as + row * AST + ch * 8),
                       A + (long long)(m0 + row) * K + k0 + ch * 8);
        }
#pragma unroll
        for (int i = 0; i < 4; i++) {
            int f = tid + i * 256;
            int row = f >> 2, ch = f & 3;
            cp_async16(smem_u32(bs + row * AST + ch * 8),
                       Bm + (long long)(n0 + row) * K + k0 + ch * 8);
        }
        asm volatile("cp.async.commit_group;");
    };

    load_stage(0, 0);
    load_stage(1, BKK);

    for (int c = 0; c < nK; c++) {
        if (c + 1 < nK) asm volatile("cp.async.wait_group 1;");
        else            asm volatile("cp.async.wait_group 0;");
        __syncthreads();

        if (c + 2 < nK) load_stage((c + 2) % MM_STAGES, (long long)(c + 2) * BKK);

        const int buf = c % MM_STAGES;
        const __nv_bfloat16* asb = As + buf * BM * AST;
        const __nv_bfloat16* bsb = Bs + buf * BN * AST;
#pragma unroll
        for (int ks = 0; ks < 2; ks++) {
            uint32_t af[4][4], bfq[4][4];
#pragma unroll
            for (int mt = 0; mt < 4; mt++)
                ldsm_x4(af[mt], smem_u32(asb + (wm + mt * 16 + lr) * AST + ks * 16 + lc));
#pragma unroll
            for (int ng = 0; ng < 4; ng++)
                ldsm_x4(bfq[ng], smem_u32(bsb + (wn + ng * 16 + lr) * AST + ks * 16 + lc));
#pragma unroll
            for (int mt = 0; mt < 4; mt++)
#pragma unroll
                for (int nt = 0; nt < 8; nt++) {
                    const int ng = nt >> 1, sub = nt & 1;
                    mma16816(acc[mt][nt], af[mt], bfq[ng][sub], bfq[ng][sub + 2]);
                }
        }
        // NOTE: no bottom barrier — the top-of-loop __syncthreads() (reached only
        // after every thread finishes this compute phase) orders reads of stage
        // (c%3) before the load_stage((c+3)%3 == c%3) issued in iteration c+1.
    }

    // ---- epilogue (fragment layout: lane = 4*g + tg; rows g, g+8; cols 2tg,2tg+1)
    const int g = lane >> 2, tg = lane & 3;
#pragma unroll
    for (int mt = 0; mt < 4; mt++) {
#pragma unroll
        for (int nt = 0; nt < 8; nt++) {
            const int row = m0 + wm + mt * 16 + g;
            const int col = n0 + wn + nt * 8 + 2 * tg;
            const long long o0 = (long long)row * N + col;
            const long long o1 = (long long)(row + 8) * N + col;
            float x0 = acc[mt][nt][0], x1 = acc[mt][nt][1];
            float x2 = acc[mt][nt][2], x3 = acc[mt][nt][3];
            if (BMODE == 1) {
                float b0 = bias[col], b1 = bias[col + 1];
                x0 += b0; x1 += b1; x2 += b0; x3 += b1;
            } else if (BMODE == 2) {
                float b0 = bias[row], b1 = bias[row + 8];
                x0 += b0; x1 += b0; x2 += b1; x3 += b1;
            }
            if (EPI == 0) {
                __nv_bfloat16* o = (__nv_bfloat16*)Out + (long long)b * sO;
                *(__nv_bfloat162*)(o + o0) = __floats2bfloat162_rn(x0, x1);
                *(__nv_bfloat162*)(o + o1) = __floats2bfloat162_rn(x2, x3);
            } else {
                float* o = (float*)Out + (long long)b * sO;
                if (EPI == 2) {
                    const float* rs = Res + (long long)b * sO;
                    float2 r0 = *(const float2*)(rs + o0);
                    float2 r1 = *(const float2*)(rs + o1);
                    x0 += r0.x; x1 += r0.y; x2 += r1.x; x3 += r1.y;
                }
                *(float2*)(o + o0) = make_float2(x0, x1);
                *(float2*)(o + o1) = make_float2(x2, x3);
            }
        }
    }
}

// ---------------- elementwise fp32 -> bf16 convert ---------------------------
__global__ __launch_bounds__(256) void cvt_bf16_kernel(const float4* __restrict__ in,
                                                       __nv_bfloat162* __restrict__ out,
                                                       int n4)
{
    int i = blockIdx.x * 256 + threadIdx.x;
    if (i < n4) {
        float4 v = in[i];
        out[2 * i]     = __floats2bfloat162_rn(v.x, v.y);
        out[2 * i + 1] = __floats2bfloat162_rn(v.z, v.w);
    }
}

// ---------------- tiled transpose (R,C) -> (C,R) bf16 ------------------------
__global__ __launch_bounds__(256)
void transpose_bf16_kernel(const float* __restrict__ in, __nv_bfloat16* __restrict__ out,
                           int R, int Cc, long long sIn, long long sOut)
{
    __shared__ float t[32][33];
    const int b = blockIdx.z;
    const float* I = in + sIn * b;
    __nv_bfloat16* O = out + sOut * b;
    const int c0 = blockIdx.x * 32, r0 = blockIdx.y * 32;
    const int tx = threadIdx.x & 31, ty = threadIdx.x >> 5;
#pragma unroll
    for (int i = 0; i < 32; i += 8)
        t[ty + i][tx] = I[(long long)(r0 + ty + i) * Cc + c0 + tx];
    __syncthreads();
#pragma unroll
    for (int i = 0; i < 32; i += 8)
        O[(long long)(c0 + ty + i) * R + r0 + tx] = __float2bfloat16(t[tx][ty + i]);
}

// ---------------- softmax(lam) -> g_w ; bqbk = bq.bk -------------------------
__global__ void prep_weights_kernel(const float* __restrict__ lam,
                                    const float* __restrict__ bq,
                                    const float* __restrict__ bk)
{
    const int lane = threadIdx.x;
    float s = 0.f;
    for (int c = lane; c < C_; c += 32) s += bq[c] * bk[c];
#pragma unroll
    for (int off = 16; off > 0; off >>= 1) s += __shfl_xor_sync(0xffffffffu, s, off);
    if (lane == 0) {
        g_bqbk = s;
        float m = fmaxf(lam[0], fmaxf(lam[1], lam[2]));
        float e0 = __expf(lam[0] - m);
        float e1 = __expf(lam[1] - m);
        float e2 = __expf(lam[2] - m);
        float t = e0 + e1 + e2;
        g_w[0] = e0 / t; g_w[1] = e1 / t; g_w[2] = e2 / t;
    }
}

// ---------------- out[r] = M[r,:] . v   (fp32, warp per row) -----------------
__global__ __launch_bounds__(256)
void dotrows_kernel(const float* __restrict__ M, const float* __restrict__ v,
                    float* __restrict__ out, int cols)
{
    int row = blockIdx.x * 8 + (threadIdx.x >> 5);
    int lane = threadIdx.x & 31;
    const float* mr = M + (long long)row * cols;
    float s = 0.f;
    for (int c = lane; c < cols; c += 32) s += mr[c] * v[c];
#pragma unroll
    for (int off = 16; off > 0; off >>= 1) s += __shfl_xor_sync(0xffffffffu, s, off);
    if (lane == 0) out[row] = s;
}

// ---------------- bias[b,l] = t_tok[b,l,:] . wkbq + bqbk ---------------------
__global__ __launch_bounds__(256) void bias_kernel(const float* __restrict__ t_tok)
{
    int row = blockIdx.x * 8 + (threadIdx.x >> 5);   // 0 .. B*L-1
    int lane = threadIdx.x & 31;
    const float* tr = t_tok + (long long)row * CT_;
    float s = 0.f;
    for (int c = lane; c < CT_; c += 32) s += tr[c] * g_wkbq[c];
#pragma unroll
    for (int off = 16; off > 0; off >>= 1) s += __shfl_xor_sync(0xffffffffu, s, off);
    if (lane == 0) g_bias[row] = s + g_bqbk;
}

// ============ fused box-pool (1/3/5) + 3-way softmax + combine ==============
// Block = (y, b). Reads bf16 logits (B,L,N), pools spatially on the fly,
// softmaxes over L per (scale, x), combines with weights -> attnT (B,N,L) bf16.
#define PS 50                       // plane column pad (48 -> 50)
#define PLANE (L_ * PS)             // 25600 bf16 per plane
#define SP_SMEM (3 * PLANE * 2 + 16 * 240 * 4)   // 168960 bytes

__global__ __launch_bounds__(512) void softmax_pool_kernel()
{
    extern __shared__ char sdyn[];
    __nv_bfloat16* planes = (__nv_bfloat16*)sdyn;                    // [3][L][PS]
    float* slab = (float*)(sdyn + 3 * PLANE * sizeof(__nv_bfloat16)); // [16][240]
    __shared__ float coef[NS_][48];

    const int b = blockIdx.y;
    const int y = blockIdx.x;
    const int tid = threadIdx.x, warp = tid >> 5, lane = tid & 31;
    const float sc = 0.03125f;      // C^{-1/2}

    float* ws = slab + warp * 240;  // 5 rows x 48 cols

    // ---- Phase A: pool + bias + scale, store 3 planes (bf16)
    for (int l = warp; l < L_; l += 16) {
        __syncwarp();
        const __nv_bfloat16* src = g_logits_bf + ((long long)(b * L_ + l)) * N_;
#pragma unroll
        for (int r = 0; r < 5; r++) {
            const int yy = y - 2 + r;
            if (lane < 12) {
                float4 o;
                if (yy >= 0 && yy < H_) {
                    uint2 u = *(const uint2*)(src + yy * W_ + lane * 4);
                    __nv_bfloat162 p0 = *(__nv_bfloat162*)&u.x;
                    __nv_bfloat162 p1 = *(__nv_bfloat162*)&u.y;
                    o.x = __bfloat162float(p0.x); o.y = __bfloat162float(p0.y);
                    o.z = __bfloat162float(p1.x); o.w = __bfloat162float(p1.y);
                } else {
                    o = make_float4(0.f, 0.f, 0.f, 0.f);
                }
                *(float4*)(ws + r * 48 + lane * 4) = o;
            }
        }
        __syncwarp();
        const float bias = g_bias[b * L_ + l];
        if (lane < 24) {
            const int x0 = lane * 2;
            float c0 = ws[96 + x0], c1 = ws[96 + x0 + 1];
            float s3a = 0.f, s3b = 0.f, s5a = 0.f, s5b = 0.f;
#pragma unroll
            for (int r = 0; r < 5; r++) {
                float v[6];
#pragma unroll
                for (int d = 0; d < 6; d++) {
                    const int xx = x0 - 2 + d;
                    v[d] = (xx >= 0 && xx < W_) ? ws[r * 48 + xx] : 0.f;
                }
                s5a += v[0] + v[1] + v[2] + v[3] + v[4];
                s5b += v[1] + v[2] + v[3] + v[4] + v[5];
                if (r >= 1 && r <= 3) {
                    s3a += v[1] + v[2] + v[3];
                    s3b += v[2] + v[3] + v[4];
                }
            }
            const int base = l * PS + x0;
            *(__nv_bfloat162*)(planes + 0 * PLANE + base) =
                __floats2bfloat162_rn((c0 + bias) * sc, (c1 + bias) * sc);
            *(__nv_bfloat162*)(planes + 1 * PLANE + base) =
                __floats2bfloat162_rn((s3a * (1.f / 9.f) + bias) * sc,
                                      (s3b * (1.f / 9.f) + bias) * sc);
            *(__nv_bfloat162*)(planes + 2 * PLANE + base) =
                __floats2bfloat162_rn((s5a * (1.f / 25.f) + bias) * sc,
                                      (s5b * (1.f / 25.f) + bias) * sc);
        }
    }
    __syncthreads();

    // ---- Phase B: per (scale, x) column softmax over L (warp per column)
    for (int col = warp; col < NS_ * 48; col += 16) {
        const int s = col / 48, x = col - s * 48;
        __nv_bfloat16* base = planes + s * PLANE + x;
        float vals[16];
        float mx = -1e30f;
#pragma unroll
        for (int r = 0; r < 16; r++) {
            vals[r] = __bfloat162float(base[(lane + r * 32) * PS]);
            mx = fmaxf(mx, vals[r]);
        }
#pragma unroll
        for (int off = 16; off > 0; off >>= 1)
            mx = fmaxf(mx, __shfl_xor_sync(0xffffffffu, mx, off));
        float ssum = 0.f;
#pragma unroll
        for (int r = 0; r < 16; r++) {
            float e = __expf(vals[r] - mx);
            base[(lane + r * 32) * PS] = __float2bfloat16(e);
            ssum += e;
        }
#pragma unroll
        for (int off = 16; off > 0; off >>= 1)
            ssum += __shfl_xor_sync(0xffffffffu, ssum, off);
        if (lane == 0) coef[s][x] = g_w[s] / ssum;
    }
    __syncthreads();

    // ---- Phase C: weighted combine -> attnT (B, N, L) bf16
    for (int x = warp; x < 48; x += 16) {
        const float c0 = coef[0][x], c1 = coef[1][x], c2 = coef[2][x];
        __nv_bfloat16* dst = g_attnT_bf + ((long long)(b * N_ + y * W_ + x)) * L_;
        for (int l = lane; l < L_; l += 32) {
            const int base = l * PS + x;
            float v = __bfloat162float(planes[0 * PLANE + base]) * c0
                    + __bfloat162float(planes[1 * PLANE + base]) * c1
                    + __bfloat162float(planes[2 * PLANE + base]) * c2;
            dst[l] = __float2bfloat16(v);
        }
    }
}

// ---------------- t_tok passthrough -----------------------------------------
__global__ __launch_bounds__(256) void copy_kernel(const float4* __restrict__ src,
                                                   float4* __restrict__ dst, int n4)
{
    int i = blockIdx.x * 256 + threadIdx.x;
    if (i < n4) dst[i] = src[i];
}

// ---------------- host ------------------------------------------------------
extern "C" void kernel_launch(void* const* d_in, const int* in_sizes, int n_in,
                              void* d_out, int out_size)
{
    const float* v_feat = (const float*)d_in[0];   // (B,C,H,W)
    const float* t_tok  = (const float*)d_in[1];   // (B,L,Ct)
    const float* Wq     = (const float*)d_in[2];   // (C,C)
    const float* bq     = (const float*)d_in[3];
    const float* Wk     = (const float*)d_in[4];   // (Ct,C)
    const float* bk     = (const float*)d_in[5];
    const float* Wv     = (const float*)d_in[6];   // (Ct,C)
    const float* bv     = (const float*)d_in[7];
    const float* lam    = (const float*)d_in[8];   // (3,)
    float* out = (float*)d_out;

    __nv_bfloat16 *p_ttok, *p_Wq, *p_Wk, *p_WvT, *p_WkqT, *p_vtxtT, *p_vflat,
                  *p_kq, *p_attnT, *p_logits;
    float *p_wkbq, *p_bkq;
    cudaGetSymbolAddress((void**)&p_ttok,  g_ttok_bf);
    cudaGetSymbolAddress((void**)&p_Wq,    g_Wq_bf);
    cudaGetSymbolAddress((void**)&p_Wk,    g_Wk_bf);
    cudaGetSymbolAddress((void**)&p_WvT,   g_WvT);
    cudaGetSymbolAddress((void**)&p_WkqT,  g_WkqT);
    cudaGetSymbolAddress((void**)&p_vtxtT, g_vtxtT_bf);
    cudaGetSymbolAddress((void**)&p_vflat, g_vflat_bf);
    cudaGetSymbolAddress((void**)&p_kq,    g_kq_bf);
    cudaGetSymbolAddress((void**)&p_attnT, g_attnT_bf);
    cudaGetSymbolAddress((void**)&p_logits, g_logits_bf);
    cudaGetSymbolAddress((void**)&p_wkbq,  g_wkbq);
    cudaGetSymbolAddress((void**)&p_bkq,   g_bkq);

    cudaFuncSetAttribute(mm_bf16<0, 0>, cudaFuncAttributeMaxDynamicSharedMemorySize, MM_SMEM);
    cudaFuncSetAttribute(mm_bf16<0, 1>, cudaFuncAttributeMaxDynamicSharedMemorySize, MM_SMEM);
    cudaFuncSetAttribute(mm_bf16<0, 2>, cudaFuncAttributeMaxDynamicSharedMemorySize, MM_SMEM);
    cudaFuncSetAttribute(mm_bf16<2, 0>, cudaFuncAttributeMaxDynamicSharedMemorySize, MM_SMEM);
    cudaFuncSetAttribute(softmax_pool_kernel,
                         cudaFuncAttributeMaxDynamicSharedMemorySize, SP_SMEM);

    prep_weights_kernel<<<1, 32>>>(lam, bq, bk);

    // bf16 conversions (original layouts)
    {
        int n4 = (B_ * L_ * CT_) / 4;
        cvt_bf16_kernel<<<(n4 + 255) / 256, 256>>>((const float4*)t_tok,
                                                   (__nv_bfloat162*)p_ttok, n4);
        int w4 = (C_ * C_) / 4;
        cvt_bf16_kernel<<<(w4 + 255) / 256, 256>>>((const float4*)Wq,
                                                   (__nv_bfloat162*)p_Wq, w4);
        int k4 = (CT_ * C_) / 4;
        cvt_bf16_kernel<<<(k4 + 255) / 256, 256>>>((const float4*)Wk,
                                                   (__nv_bfloat162*)p_Wk, k4);
    }
    // Wv -> WvT bf16 (C, Ct)
    transpose_bf16_kernel<<<dim3(C_ / 32, CT_ / 32, 1), 256>>>(Wv, p_WvT, CT_, C_, 0, 0);
    // v_feat (B,C,N) -> v_flat (B,N,C) bf16
    transpose_bf16_kernel<<<dim3(N_ / 32, C_ / 32, B_), 256>>>(
        v_feat, p_vflat, C_, N_, (long long)C_ * N_, (long long)N_ * C_);

    // vector precomputes (exact fp32)
    dotrows_kernel<<<CT_ / 8, 256>>>(Wk, bq, p_wkbq, C_);   // wkbq[ct] = Wk[ct,:].bq
    dotrows_kernel<<<C_ / 8, 256>>>(Wq, bk, p_bkq, C_);     // bkq[cin] = Wq[cin,:].bk
    bias_kernel<<<(B_ * L_) / 8, 256>>>(t_tok);             // bias = t_tok.wkbq + bq.bk

    // WkqT[cin, ct] = sum_cout Wq[cin,cout] * Wk[ct,cout]   (M=C, N=Ct, K=C)
    mm_bf16<0, 0><<<dim3(CT_ / BN, C_ / BM, 1), 256, MM_SMEM>>>(
        p_Wq, p_Wk, p_WkqT, nullptr, nullptr, CT_, C_, 0, 0, 0);

    // kq = t_tok @ WkqT^T + bkq  -> bf16 (B*L, C)   (M=B*L, N=C, K=Ct)
    mm_bf16<0, 1><<<dim3(C_ / BN, (B_ * L_) / BM, 1), 256, MM_SMEM>>>(
        p_ttok, p_WkqT, p_kq, p_bkq, nullptr, C_, CT_, 0, 0, 0);

    // vtxtT[b] = WvT @ t_tok[b]^T + bv (row bias) -> bf16 (B,C,L)  (M=C,N=L,K=Ct)
    mm_bf16<0, 2><<<dim3(L_ / BN, C_ / BM, B_), 256, MM_SMEM>>>(
        p_WvT, p_ttok, p_vtxtT, bv, nullptr, L_, CT_,
        0, (long long)L_ * CT_, (long long)C_ * L_);

    // logits[b] = kq[b] @ v_flat[b]^T  -> bf16 (B,L,N)
    mm_bf16<0, 0><<<dim3(N_ / BN, L_ / BM, B_), 256, MM_SMEM>>>(
        p_kq, p_vflat, p_logits, nullptr, nullptr, N_, C_,
        (long long)L_ * C_, (long long)N_ * C_, (long long)L_ * N_);

    // fused pool + softmax + combine -> attnT (B,N,L) bf16
    softmax_pool_kernel<<<dim3(H_, B_), 512, SP_SMEM>>>();

    // out_vis[b] = v_txt[b]^T @ attn[b] + v_feat[b]  -> fp32 (B,C,N)
    mm_bf16<2, 0><<<dim3(N_ / BN, C_ / BM, B_), 256, MM_SMEM>>>(
        p_vtxtT, p_attnT, out, nullptr, v_feat, N_, L_,
        (long long)C_ * L_, (long long)N_ * L_, (long long)C_ * N_);

    // t_tok passthrough
    int n4 = (B_ * L_ * CT_) / 4;
    copy_kernel<<<(n4 + 255) / 256, 256>>>(
        (const float4*)t_tok, (float4*)(out + (size_t)B_ * C_ * N_), n4);
}

// round 15
// speedup vs baseline: 5.0979x; 1.0030x over previous
#include <cuda_runtime.h>
#include <cuda_bf16.h>
#include <cstdint>
#include <math.h>

// Shapes (fixed by the problem)
#define B_  16
#define C_  1024
#define H_  48
#define W_  48
#define N_  2304   // H*W
#define L_  512
#define CT_ 768
#define NS_ 3

// ---------------- scratch (device globals; no allocation allowed) ----------
__device__ __nv_bfloat16 g_ttok_bf[B_ * L_ * CT_];     // (B,L,Ct)
__device__ __nv_bfloat16 g_Wq_bf[C_ * C_];             // (Cin,Cout) original
__device__ __nv_bfloat16 g_Wk_bf[CT_ * C_];            // (Ct,C) original
__device__ __nv_bfloat16 g_WvT[C_ * CT_];              // (C,Ct)
__device__ __nv_bfloat16 g_WkqT[C_ * CT_];             // (C,Ct)  Wq . Wk^T
__device__ __nv_bfloat16 g_vtxtT_bf[B_ * C_ * L_];     // (B,C,L) v_txt^T (+bv)
__device__ __nv_bfloat16 g_vflat_bf[B_ * N_ * C_];     // (B,N,C)
__device__ __nv_bfloat16 g_kq_bf[B_ * L_ * C_];        // (B,L,C)
__device__ __nv_bfloat16 g_attnT_bf[B_ * N_ * L_];     // (B,N,L) combined attn^T
__device__ __nv_bfloat16 g_logits_bf[B_ * L_ * N_];    // (B,L,N) bf16
__device__ float g_bias[B_ * L_];                      // bq . k_txt[b,l]
__device__ float g_wkbq[CT_];                          // Wk @ bq
__device__ float g_bkq[C_];                            // Wq @ bk  (per cin)
__device__ float g_w[NS_];                             // softmax(lam)
__device__ float g_bqbk;                               // bq . bk

// ======================= helpers ============================================
__device__ __forceinline__ uint32_t smem_u32(const void* p) {
    uint32_t a;
    asm("{ .reg .u64 t; cvta.to.shared.u64 t, %1; cvt.u32.u64 %0, t; }"
        : "=r"(a) : "l"(p));
    return a;
}
__device__ __forceinline__ void ldsm_x4(uint32_t* f, uint32_t addr) {
    asm volatile("ldmatrix.sync.aligned.m8n8.x4.shared.b16 {%0,%1,%2,%3}, [%4];"
                 : "=r"(f[0]), "=r"(f[1]), "=r"(f[2]), "=r"(f[3]) : "r"(addr));
}
__device__ __forceinline__ void mma16816(float* d, const uint32_t* a,
                                         uint32_t b0, uint32_t b1) {
    asm volatile("mma.sync.aligned.m16n8k16.row.col.f32.bf16.bf16.f32 "
                 "{%0,%1,%2,%3}, {%4,%5,%6,%7}, {%8,%9}, {%0,%1,%2,%3};"
                 : "+f"(d[0]), "+f"(d[1]), "+f"(d[2]), "+f"(d[3])
                 : "r"(a[0]), "r"(a[1]), "r"(a[2]), "r"(a[3]), "r"(b0), "r"(b1));
}
__device__ __forceinline__ void cp_async16(uint32_t dst, const void* src) {
    asm volatile("cp.async.cg.shared.global [%0], [%1], 16;" :: "r"(dst), "l"(src));
}

// ======================= HMMA bf16 batched GEMM =============================
// C[m,n] = sum_k A[m,k] * Bop[n,k]; A (M,K) bf16 K-major, Bop (N,K) bf16 K-major.
// CTA tile 128x256x32, 3-stage cp.async pipeline, 256 threads
// (8 warps, 2x4 grid of 64x64 warp tiles).
// EPI: 0 = bf16 out, 1 = fp32 out, 2 = fp32 out + Res add.
// BMODE: 0 = none, 1 = +bias[n] (column), 2 = +bias[m] (row).
#define BM 128
#define BN 256
#define BKK 32
#define AST 40   // bf16 elems per smem row (32 + 8 pad) => 80B stride
#define MM_STAGES 3
#define MM_SMEM (MM_STAGES * (BM + BN) * AST * 2)   // 92160 bytes

template <int EPI, int BMODE>
__global__ __launch_bounds__(256)
void mm_bf16(const __nv_bfloat16* __restrict__ A, const __nv_bfloat16* __restrict__ Bm,
             void* __restrict__ Out, const float* __restrict__ bias,
             const float* __restrict__ Res,
             int N, int K, long long sA, long long sB, long long sO)
{
    extern __shared__ __nv_bfloat16 dsm[];
    __nv_bfloat16* As = dsm;                        // [3][BM*AST]
    __nv_bfloat16* Bs = dsm + MM_STAGES * BM * AST; // [3][BN*AST]

    const int b = blockIdx.z;
    A  += sA * b;
    Bm += sB * b;
    const int m0 = blockIdx.y * BM;
    const int n0 = blockIdx.x * BN;
    const int tid = threadIdx.x, wid = tid >> 5, lane = tid & 31;
    const int wm = (wid & 1) * 64;    // warp m offset within tile
    const int wn = (wid >> 1) * 64;   // warp n offset within tile

    float acc[4][8][4];
#pragma unroll
    for (int i = 0; i < 4; i++)
#pragma unroll
        for (int j = 0; j < 8; j++)
#pragma unroll
            for (int r = 0; r < 4; r++) acc[i][j][r] = 0.f;

    const int nK = K / BKK;
    const int lr = lane & 15;
    const int lc = (lane >> 4) * 8;

    auto load_stage = [&](int st, long long k0) {
        __nv_bfloat16* as = As + st * BM * AST;
        __nv_bfloat16* bs = Bs + st * BN * AST;
#pragma unroll
        for (int i = 0; i < 2; i++) {
            int f = tid + i * 256;
            int row = f >> 2, ch = f & 3;
            cp_async16(smem_u32(as + row * AST + ch * 8),
                       A + (long long)(m0 + row) * K + k0 + ch * 8);
        }
#pragma unroll
        for (int i = 0; i < 4; i++) {
            int f = tid + i * 256;
            int row = f >> 2, ch = f & 3;
            cp_async16(smem_u32(bs + row * AST + ch * 8),
                       Bm + (long long)(n0 + row) * K + k0 + ch * 8);
        }
        asm volatile("cp.async.commit_group;");
    };

    load_stage(0, 0);
    load_stage(1, BKK);

    for (int c = 0; c < nK; c++) {
        if (c + 1 < nK) asm volatile("cp.async.wait_group 1;");
        else            asm volatile("cp.async.wait_group 0;");
        __syncthreads();

        if (c + 2 < nK) load_stage((c + 2) % MM_STAGES, (long long)(c + 2) * BKK);

        const int buf = c % MM_STAGES;
        const __nv_bfloat16* asb = As + buf * BM * AST;
        const __nv_bfloat16* bsb = Bs + buf * BN * AST;
#pragma unroll
        for (int ks = 0; ks < 2; ks++) {
            uint32_t af[4][4], bfq[4][4];
#pragma unroll
            for (int mt = 0; mt < 4; mt++)
                ldsm_x4(af[mt], smem_u32(asb + (wm + mt * 16 + lr) * AST + ks * 16 + lc));
#pragma unroll
            for (int ng = 0; ng < 4; ng++)
                ldsm_x4(bfq[ng], smem_u32(bsb + (wn + ng * 16 + lr) * AST + ks * 16 + lc));
#pragma unroll
            for (int mt = 0; mt < 4; mt++)
#pragma unroll
                for (int nt = 0; nt < 8; nt++) {
                    const int ng = nt >> 1, sub = nt & 1;
                    mma16816(acc[mt][nt], af[mt], bfq[ng][sub], bfq[ng][sub + 2]);
                }
        }
        // NOTE: no bottom barrier — the top-of-loop __syncthreads() (reached only
        // after every thread finishes this compute phase) orders reads of stage
        // (c%3) before the load_stage((c+3)%3 == c%3) issued in iteration c+1.
    }

    // ---- epilogue (fragment layout: lane = 4*g + tg; rows g, g+8; cols 2tg,2tg+1)
    const int g = lane >> 2, tg = lane & 3;
#pragma unroll
    for (int mt = 0; mt < 4; mt++) {
#pragma unroll
        for (int nt = 0; nt < 8; nt++) {
            const int row = m0 + wm + mt * 16 + g;
            const int col = n0 + wn + nt * 8 + 2 * tg;
            const long long o0 = (long long)row * N + col;
            const long long o1 = (long long)(row + 8) * N + col;
            float x0 = acc[mt][nt][0], x1 = acc[mt][nt][1];
            float x2 = acc[mt][nt][2], x3 = acc[mt][nt][3];
            if (BMODE == 1) {
                float b0 = bias[col], b1 = bias[col + 1];
                x0 += b0; x1 += b1; x2 += b0; x3 += b1;
            } else if (BMODE == 2) {
                float b0 = bias[row], b1 = bias[row + 8];
                x0 += b0; x1 += b0; x2 += b1; x3 += b1;
            }
            if (EPI == 0) {
                __nv_bfloat16* o = (__nv_bfloat16*)Out + (long long)b * sO;
                *(__nv_bfloat162*)(o + o0) = __floats2bfloat162_rn(x0, x1);
                *(__nv_bfloat162*)(o + o1) = __floats2bfloat162_rn(x2, x3);
            } else {
                float* o = (float*)Out + (long long)b * sO;
                if (EPI == 2) {
                    const float* rs = Res + (long long)b * sO;
                    float2 r0 = *(const float2*)(rs + o0);
                    float2 r1 = *(const float2*)(rs + o1);
                    x0 += r0.x; x1 += r0.y; x2 += r1.x; x3 += r1.y;
                }
                *(float2*)(o + o0) = make_float2(x0, x1);
                *(float2*)(o + o1) = make_float2(x2, x3);
            }
        }
    }
}

// ---------------- elementwise fp32 -> bf16 convert ---------------------------
__global__ __launch_bounds__(256) void cvt_bf16_kernel(const float4* __restrict__ in,
                                                       __nv_bfloat162* __restrict__ out,
                                                       int n4)
{
    int i = blockIdx.x * 256 + threadIdx.x;
    if (i < n4) {
        float4 v = in[i];
        out[2 * i]     = __floats2bfloat162_rn(v.x, v.y);
        out[2 * i + 1] = __floats2bfloat162_rn(v.z, v.w);
    }
}

// ---------------- tiled transpose (R,C) -> (C,R) bf16 ------------------------
__global__ __launch_bounds__(256)
void transpose_bf16_kernel(const float* __restrict__ in, __nv_bfloat16* __restrict__ out,
                           int R, int Cc, long long sIn, long long sOut)
{
    __shared__ float t[32][33];
    const int b = blockIdx.z;
    const float* I = in + sIn * b;
    __nv_bfloat16* O = out + sOut * b;
    const int c0 = blockIdx.x * 32, r0 = blockIdx.y * 32;
    const int tx = threadIdx.x & 31, ty = threadIdx.x >> 5;
#pragma unroll
    for (int i = 0; i < 32; i += 8)
        t[ty + i][tx] = I[(long long)(r0 + ty + i) * Cc + c0 + tx];
    __syncthreads();
#pragma unroll
    for (int i = 0; i < 32; i += 8)
        O[(long long)(c0 + ty + i) * R + r0 + tx] = __float2bfloat16(t[tx][ty + i]);
}

// ---------------- softmax(lam) -> g_w ; bqbk = bq.bk -------------------------
__global__ void prep_weights_kernel(const float* __restrict__ lam,
                                    const float* __restrict__ bq,
                                    const float* __restrict__ bk)
{
    const int lane = threadIdx.x;
    float s = 0.f;
    for (int c = lane; c < C_; c += 32) s += bq[c] * bk[c];
#pragma unroll
    for (int off = 16; off > 0; off >>= 1) s += __shfl_xor_sync(0xffffffffu, s, off);
    if (lane == 0) {
        g_bqbk = s;
        float m = fmaxf(lam[0], fmaxf(lam[1], lam[2]));
        float e0 = __expf(lam[0] - m);
        float e1 = __expf(lam[1] - m);
        float e2 = __expf(lam[2] - m);
        float t = e0 + e1 + e2;
        g_w[0] = e0 / t; g_w[1] = e1 / t; g_w[2] = e2 / t;
    }
}

// ---------------- out[r] = M[r,:] . v   (fp32, warp per row) -----------------
__global__ __launch_bounds__(256)
void dotrows_kernel(const float* __restrict__ M, const float* __restrict__ v,
                    float* __restrict__ out, int cols)
{
    int row = blockIdx.x * 8 + (threadIdx.x >> 5);
    int lane = threadIdx.x & 31;
    const float* mr = M + (long long)row * cols;
    float s = 0.f;
    for (int c = lane; c < cols; c += 32) s += mr[c] * v[c];
#pragma unroll
    for (int off = 16; off > 0; off >>= 1) s += __shfl_xor_sync(0xffffffffu, s, off);
    if (lane == 0) out[row] = s;
}

// ---------------- bias[b,l] = t_tok[b,l,:] . wkbq + bqbk ---------------------
__global__ __launch_bounds__(256) void bias_kernel(const float* __restrict__ t_tok)
{
    int row = blockIdx.x * 8 + (threadIdx.x >> 5);   // 0 .. B*L-1
    int lane = threadIdx.x & 31;
    const float* tr = t_tok + (long long)row * CT_;
    float s = 0.f;
    for (int c = lane; c < CT_; c += 32) s += tr[c] * g_wkbq[c];
#pragma unroll
    for (int off = 16; off > 0; off >>= 1) s += __shfl_xor_sync(0xffffffffu, s, off);
    if (lane == 0) g_bias[row] = s + g_bqbk;
}

// ============ fused box-pool (1/3/5) + 3-way softmax + combine ==============
// Block = (y, b). Reads bf16 logits (B,L,N), pools spatially on the fly,
// softmaxes over L per (scale, x), combines with weights -> attnT (B,N,L) bf16.
#define PS 50                       // plane column pad (48 -> 50)
#define PLANE (L_ * PS)             // 25600 bf16 per plane
#define SP_SMEM (3 * PLANE * 2 + 16 * 240 * 4)   // 168960 bytes

__global__ __launch_bounds__(512) void softmax_pool_kernel()
{
    extern __shared__ char sdyn[];
    __nv_bfloat16* planes = (__nv_bfloat16*)sdyn;                    // [3][L][PS]
    float* slab = (float*)(sdyn + 3 * PLANE * sizeof(__nv_bfloat16)); // [16][240]
    __shared__ float coef[NS_][48];

    const int b = blockIdx.y;
    const int y = blockIdx.x;
    const int tid = threadIdx.x, warp = tid >> 5, lane = tid & 31;
    const float sc = 0.03125f;      // C^{-1/2}

    float* ws = slab + warp * 240;  // 5 rows x 48 cols

    // ---- Phase A: pool + bias + scale, store 3 planes (bf16)
    for (int l = warp; l < L_; l += 16) {
        __syncwarp();
        const __nv_bfloat16* src = g_logits_bf + ((long long)(b * L_ + l)) * N_;
#pragma unroll
        for (int r = 0; r < 5; r++) {
            const int yy = y - 2 + r;
            if (lane < 12) {
                float4 o;
                if (yy >= 0 && yy < H_) {
                    uint2 u = *(const uint2*)(src + yy * W_ + lane * 4);
                    __nv_bfloat162 p0 = *(__nv_bfloat162*)&u.x;
                    __nv_bfloat162 p1 = *(__nv_bfloat162*)&u.y;
                    o.x = __bfloat162float(p0.x); o.y = __bfloat162float(p0.y);
                    o.z = __bfloat162float(p1.x); o.w = __bfloat162float(p1.y);
                } else {
                    o = make_float4(0.f, 0.f, 0.f, 0.f);
                }
                *(float4*)(ws + r * 48 + lane * 4) = o;
            }
        }
        __syncwarp();
        const float bias = g_bias[b * L_ + l];
        if (lane < 24) {
            const int x0 = lane * 2;
            float c0 = ws[96 + x0], c1 = ws[96 + x0 + 1];
            float s3a = 0.f, s3b = 0.f, s5a = 0.f, s5b = 0.f;
#pragma unroll
            for (int r = 0; r < 5; r++) {
                float v[6];
#pragma unroll
                for (int d = 0; d < 6; d++) {
                    const int xx = x0 - 2 + d;
                    v[d] = (xx >= 0 && xx < W_) ? ws[r * 48 + xx] : 0.f;
                }
                s5a += v[0] + v[1] + v[2] + v[3] + v[4];
                s5b += v[1] + v[2] + v[3] + v[4] + v[5];
                if (r >= 1 && r <= 3) {
                    s3a += v[1] + v[2] + v[3];
                    s3b += v[2] + v[3] + v[4];
                }
            }
            const int base = l * PS + x0;
            *(__nv_bfloat162*)(planes + 0 * PLANE + base) =
                __floats2bfloat162_rn((c0 + bias) * sc, (c1 + bias) * sc);
            *(__nv_bfloat162*)(planes + 1 * PLANE + base) =
                __floats2bfloat162_rn((s3a * (1.f / 9.f) + bias) * sc,
                                      (s3b * (1.f / 9.f) + bias) * sc);
            *(__nv_bfloat162*)(planes + 2 * PLANE + base) =
                __floats2bfloat162_rn((s5a * (1.f / 25.f) + bias) * sc,
                                      (s5b * (1.f / 25.f) + bias) * sc);
        }
    }
    __syncthreads();

    // ---- Phase B: per (scale, x) column softmax over L (warp per column)
    for (int col = warp; col < NS_ * 48; col += 16) {
        const int s = col / 48, x = col - s * 48;
        __nv_bfloat16* base = planes + s * PLANE + x;
        float vals[16];
        float mx = -1e30f;
#pragma unroll
        for (int r = 0; r < 16; r++) {
            vals[r] = __bfloat162float(base[(lane + r * 32) * PS]);
            mx = fmaxf(mx, vals[r]);
        }
#pragma unroll
        for (int off = 16; off > 0; off >>= 1)
            mx = fmaxf(mx, __shfl_xor_sync(0xffffffffu, mx, off));
        float ssum = 0.f;
#pragma unroll
        for (int r = 0; r < 16; r++) {
            float e = __expf(vals[r] - mx);
            base[(lane + r * 32) * PS] = __float2bfloat16(e);
            ssum += e;
        }
#pragma unroll
        for (int off = 16; off > 0; off >>= 1)
            ssum += __shfl_xor_sync(0xffffffffu, ssum, off);
        if (lane == 0) coef[s][x] = g_w[s] / ssum;
    }
    __syncthreads();

    // ---- Phase C: weighted combine -> attnT (B, N, L) bf16
    for (int x = warp; x < 48; x += 16) {
        const float c0 = coef[0][x], c1 = coef[1][x], c2 = coef[2][x];
        __nv_bfloat16* dst = g_attnT_bf + ((long long)(b * N_ + y * W_ + x)) * L_;
        for (int l = lane; l < L_; l += 32) {
            const int base = l * PS + x;
            float v = __bfloat162float(planes[0 * PLANE + base]) * c0
                    + __bfloat162float(planes[1 * PLANE + base]) * c1
                    + __bfloat162float(planes[2 * PLANE + base]) * c2;
            dst[l] = __float2bfloat16(v);
        }
    }
}

// ---------------- t_tok passthrough -----------------------------------------
__global__ __launch_bounds__(256) void copy_kernel(const float4* __restrict__ src,
                                                   float4* __restrict__ dst, int n4)
{
    int i = blockIdx.x * 256 + threadIdx.x;
    if (i < n4) dst[i] = src[i];
}

// ---------------- host ------------------------------------------------------
extern "C" void kernel_launch(void* const* d_in, const int* in_sizes, int n_in,
                              void* d_out, int out_size)
{
    const float* v_feat = (const float*)d_in[0];   // (B,C,H,W)
    const float* t_tok  = (const float*)d_in[1];   // (B,L,Ct)
    const float* Wq     = (const float*)d_in[2];   // (C,C)
    const float* bq     = (const float*)d_in[3];
    const float* Wk     = (const float*)d_in[4];   // (Ct,C)
    const float* bk     = (const float*)d_in[5];
    const float* Wv     = (const float*)d_in[6];   // (Ct,C)
    const float* bv     = (const float*)d_in[7];
    const float* lam    = (const float*)d_in[8];   // (3,)
    float* out = (float*)d_out;

    __nv_bfloat16 *p_ttok, *p_Wq, *p_Wk, *p_WvT, *p_WkqT, *p_vtxtT, *p_vflat,
                  *p_kq, *p_attnT, *p_logits;
    float *p_wkbq, *p_bkq;
    cudaGetSymbolAddress((void**)&p_ttok,  g_ttok_bf);
    cudaGetSymbolAddress((void**)&p_Wq,    g_Wq_bf);
    cudaGetSymbolAddress((void**)&p_Wk,    g_Wk_bf);
    cudaGetSymbolAddress((void**)&p_WvT,   g_WvT);
    cudaGetSymbolAddress((void**)&p_WkqT,  g_WkqT);
    cudaGetSymbolAddress((void**)&p_vtxtT, g_vtxtT_bf);
    cudaGetSymbolAddress((void**)&p_vflat, g_vflat_bf);
    cudaGetSymbolAddress((void**)&p_kq,    g_kq_bf);
    cudaGetSymbolAddress((void**)&p_attnT, g_attnT_bf);
    cudaGetSymbolAddress((void**)&p_logits, g_logits_bf);
    cudaGetSymbolAddress((void**)&p_wkbq,  g_wkbq);
    cudaGetSymbolAddress((void**)&p_bkq,   g_bkq);

    cudaFuncSetAttribute(mm_bf16<0, 0>, cudaFuncAttributeMaxDynamicSharedMemorySize, MM_SMEM);
    cudaFuncSetAttribute(mm_bf16<0, 1>, cudaFuncAttributeMaxDynamicSharedMemorySize, MM_SMEM);
    cudaFuncSetAttribute(mm_bf16<0, 2>, cudaFuncAttributeMaxDynamicSharedMemorySize, MM_SMEM);
    cudaFuncSetAttribute(mm_bf16<2, 0>, cudaFuncAttributeMaxDynamicSharedMemorySize, MM_SMEM);
    cudaFuncSetAttribute(softmax_pool_kernel,
                         cudaFuncAttributeMaxDynamicSharedMemorySize, SP_SMEM);

    prep_weights_kernel<<<1, 32>>>(lam, bq, bk);

    // bf16 conversions (original layouts)
    {
        int n4 = (B_ * L_ * CT_) / 4;
        cvt_bf16_kernel<<<(n4 + 255) / 256, 256>>>((const float4*)t_tok,
                                                   (__nv_bfloat162*)p_ttok, n4);
        int w4 = (C_ * C_) / 4;
        cvt_bf16_kernel<<<(w4 + 255) / 256, 256>>>((const float4*)Wq,
                                                   (__nv_bfloat162*)p_Wq, w4);
        int k4 = (CT_ * C_) / 4;
        cvt_bf16_kernel<<<(k4 + 255) / 256, 256>>>((const float4*)Wk,
                                                   (__nv_bfloat162*)p_Wk, k4);
    }
    // Wv -> WvT bf16 (C, Ct)
    transpose_bf16_kernel<<<dim3(C_ / 32, CT_ / 32, 1), 256>>>(Wv, p_WvT, CT_, C_, 0, 0);
    // v_feat (B,C,N) -> v_flat (B,N,C) bf16
    transpose_bf16_kernel<<<dim3(N_ / 32, C_ / 32, B_), 256>>>(
        v_feat, p_vflat, C_, N_, (long long)C_ * N_, (long long)N_ * C_);

    // vector precomputes (exact fp32)
    dotrows_kernel<<<CT_ / 8, 256>>>(Wk, bq, p_wkbq, C_);   // wkbq[ct] = Wk[ct,:].bq
    dotrows_kernel<<<C_ / 8, 256>>>(Wq, bk, p_bkq, C_);     // bkq[cin] = Wq[cin,:].bk
    bias_kernel<<<(B_ * L_) / 8, 256>>>(t_tok);             // bias = t_tok.wkbq + bq.bk

    // WkqT[cin, ct] = sum_cout Wq[cin,cout] * Wk[ct,cout]   (M=C, N=Ct, K=C)
    mm_bf16<0, 0><<<dim3(CT_ / BN, C_ / BM, 1), 256, MM_SMEM>>>(
        p_Wq, p_Wk, p_WkqT, nullptr, nullptr, CT_, C_, 0, 0, 0);

    // kq = t_tok @ WkqT^T + bkq  -> bf16 (B*L, C)   (M=B*L, N=C, K=Ct)
    mm_bf16<0, 1><<<dim3(C_ / BN, (B_ * L_) / BM, 1), 256, MM_SMEM>>>(
        p_ttok, p_WkqT, p_kq, p_bkq, nullptr, C_, CT_, 0, 0, 0);

    // vtxtT[b] = WvT @ t_tok[b]^T + bv (row bias) -> bf16 (B,C,L)  (M=C,N=L,K=Ct)
    mm_bf16<0, 2><<<dim3(L_ / BN, C_ / BM, B_), 256, MM_SMEM>>>(
        p_WvT, p_ttok, p_vtxtT, bv, nullptr, L_, CT_,
        0, (long long)L_ * CT_, (long long)C_ * L_);

    // logits[b] = kq[b] @ v_flat[b]^T  -> bf16 (B,L,N)
    mm_bf16<0, 0><<<dim3(N_ / BN, L_ / BM, B_), 256, MM_SMEM>>>(
        p_kq, p_vflat, p_logits, nullptr, nullptr, N_, C_,
        (long long)L_ * C_, (long long)N_ * C_, (long long)L_ * N_);

    // fused pool + softmax + combine -> attnT (B,N,L) bf16
    softmax_pool_kernel<<<dim3(H_, B_), 512, SP_SMEM>>>();

    // out_vis[b] = v_txt[b]^T @ attn[b] + v_feat[b]  -> fp32 (B,C,N)
    mm_bf16<2, 0><<<dim3(N_ / BN, C_ / BM, B_), 256, MM_SMEM>>>(
        p_vtxtT, p_attnT, out, nullptr, v_feat, N_, L_,
        (long long)C_ * L_, (long long)N_ * L_, (long long)C_ * N_);

    // t_tok passthrough
    int n4 = (B_ * L_ * CT_) / 4;
    copy_kernel<<<(n4 + 255) / 256, 256>>>(
        (const float4*)t_tok, (float4*)(out + (size_t)B_ * C_ * N_), n4);
}

// round 16
// speedup vs baseline: 5.1069x; 1.0018x over previous
#include <cuda_runtime.h>
#include <cuda_bf16.h>
#include <cstdint>
#include <math.h>

// Shapes (fixed by the problem)
#define B_  16
#define C_  1024
#define H_  48
#define W_  48
#define N_  2304   // H*W
#define L_  512
#define CT_ 768
#define NS_ 3

// ---------------- scratch (device globals; no allocation allowed) ----------
__device__ __nv_bfloat16 g_ttok_bf[B_ * L_ * CT_];     // (B,L,Ct)
__device__ __nv_bfloat16 g_Wq_bf[C_ * C_];             // (Cin,Cout) original
__device__ __nv_bfloat16 g_Wk_bf[CT_ * C_];            // (Ct,C) original
__device__ __nv_bfloat16 g_WvT[C_ * CT_];              // (C,Ct)
__device__ __nv_bfloat16 g_WkqT[C_ * CT_];             // (C,Ct)  Wq . Wk^T
__device__ __nv_bfloat16 g_vtxtT_bf[B_ * C_ * L_];     // (B,C,L) v_txt^T (+bv)
__device__ __nv_bfloat16 g_vflat_bf[B_ * N_ * C_];     // (B,N,C)
__device__ __nv_bfloat16 g_kq_bf[B_ * L_ * C_];        // (B,L,C)
__device__ __nv_bfloat16 g_attnT_bf[B_ * N_ * L_];     // (B,N,L) combined attn^T
__device__ __nv_bfloat16 g_logits_bf[B_ * L_ * N_];    // (B,L,N) bf16
__device__ float g_bias[B_ * L_];                      // bq . k_txt[b,l]
__device__ float g_wkbq[CT_];                          // Wk @ bq
__device__ float g_bkq[C_];                            // Wq @ bk  (per cin)
__device__ float g_w[NS_];                             // softmax(lam)
__device__ float g_bqbk;                               // bq . bk

// ======================= helpers ============================================
__device__ __forceinline__ uint32_t smem_u32(const void* p) {
    uint32_t a;
    asm("{ .reg .u64 t; cvta.to.shared.u64 t, %1; cvt.u32.u64 %0, t; }"
        : "=r"(a) : "l"(p));
    return a;
}
__device__ __forceinline__ void ldsm_x4(uint32_t* f, uint32_t addr) {
    asm volatile("ldmatrix.sync.aligned.m8n8.x4.shared.b16 {%0,%1,%2,%3}, [%4];"
                 : "=r"(f[0]), "=r"(f[1]), "=r"(f[2]), "=r"(f[3]) : "r"(addr));
}
__device__ __forceinline__ void mma16816(float* d, const uint32_t* a,
                                         uint32_t b0, uint32_t b1) {
    asm volatile("mma.sync.aligned.m16n8k16.row.col.f32.bf16.bf16.f32 "
                 "{%0,%1,%2,%3}, {%4,%5,%6,%7}, {%8,%9}, {%0,%1,%2,%3};"
                 : "+f"(d[0]), "+f"(d[1]), "+f"(d[2]), "+f"(d[3])
                 : "r"(a[0]), "r"(a[1]), "r"(a[2]), "r"(a[3]), "r"(b0), "r"(b1));
}
__device__ __forceinline__ void cp_async16(uint32_t dst, const void* src) {
    asm volatile("cp.async.cg.shared.global [%0], [%1], 16;" :: "r"(dst), "l"(src));
}

// ======================= HMMA bf16 batched GEMM =============================
// C[m,n] = sum_k A[m,k] * Bop[n,k]; A (M,K) bf16 K-major, Bop (N,K) bf16 K-major.
// CTA tile 128x256x32, 3-stage cp.async pipeline, 256 threads
// (8 warps, 2x4 grid of 64x64 warp tiles).
// EPI: 0 = bf16 out, 1 = fp32 out, 2 = fp32 out + Res add.
// BMODE: 0 = none, 1 = +bias[n] (column), 2 = +bias[m] (row).
#define BM 128
#define BN 256
#define BKK 32
#define AST 40   // bf16 elems per smem row (32 + 8 pad) => 80B stride
#define MM_STAGES 3
#define MM_SMEM (MM_STAGES * (BM + BN) * AST * 2)   // 92160 bytes

template <int EPI, int BMODE>
__global__ __launch_bounds__(256)
void mm_bf16(const __nv_bfloat16* __restrict__ A, const __nv_bfloat16* __restrict__ Bm,
             void* __restrict__ Out, const float* __restrict__ bias,
             const float* __restrict__ Res,
             int N, int K, long long sA, long long sB, long long sO)
{
    extern __shared__ __nv_bfloat16 dsm[];
    __nv_bfloat16* As = dsm;                        // [3][BM*AST]
    __nv_bfloat16* Bs = dsm + MM_STAGES * BM * AST; // [3][BN*AST]

    const int b = blockIdx.z;
    A  += sA * b;
    Bm += sB * b;
    const int m0 = blockIdx.y * BM;
    const int n0 = blockIdx.x * BN;
    const int tid = threadIdx.x, wid = tid >> 5, lane = tid & 31;
    const int wm = (wid & 1) * 64;    // warp m offset within tile
    const int wn = (wid >> 1) * 64;   // warp n offset within tile

    float acc[4][8][4];
#pragma unroll
    for (int i = 0; i < 4; i++)
#pragma unroll
        for (int j = 0; j < 8; j++)
#pragma unroll
            for (int r = 0; r < 4; r++) acc[i][j][r] = 0.f;

    const int nK = K / BKK;
    const int lr = lane & 15;
    const int lc = (lane >> 4) * 8;

    auto load_stage = [&](int st, long long k0) {
        __nv_bfloat16* as = As + st * BM * AST;
        __nv_bfloat16* bs = Bs + st * BN * AST;
#pragma unroll
        for (int i = 0; i < 2; i++) {
            int f = tid + i * 256;
            int row = f >> 2, ch = f & 3;
            cp_async16(smem_u32(as + row * AST + ch * 8),
                       A + (long long)(m0 + row) * K + k0 + ch * 8);
        }
#pragma unroll
        for (int i = 0; i < 4; i++) {
            int f = tid + i * 256;
            int row = f >> 2, ch = f & 3;
            cp_async16(smem_u32(bs + row * AST + ch * 8),
                       Bm + (long long)(n0 + row) * K + k0 + ch * 8);
        }
        asm volatile("cp.async.commit_group;");
    };

    load_stage(0, 0);
    load_stage(1, BKK);

    for (int c = 0; c < nK; c++) {
        if (c + 1 < nK) asm volatile("cp.async.wait_group 1;");
        else            asm volatile("cp.async.wait_group 0;");
        __syncthreads();

        if (c + 2 < nK) load_stage((c + 2) % MM_STAGES, (long long)(c + 2) * BKK);

        const int buf = c % MM_STAGES;
        const __nv_bfloat16* asb = As + buf * BM * AST;
        const __nv_bfloat16* bsb = Bs + buf * BN * AST;
#pragma unroll
        for (int ks = 0; ks < 2; ks++) {
            uint32_t af[4][4], bfq[4][4];
#pragma unroll
            for (int mt = 0; mt < 4; mt++)
                ldsm_x4(af[mt], smem_u32(asb + (wm + mt * 16 + lr) * AST + ks * 16 + lc));
#pragma unroll
            for (int ng = 0; ng < 4; ng++)
                ldsm_x4(bfq[ng], smem_u32(bsb + (wn + ng * 16 + lr) * AST + ks * 16 + lc));
#pragma unroll
            for (int mt = 0; mt < 4; mt++)
#pragma unroll
                for (int nt = 0; nt < 8; nt++) {
                    const int ng = nt >> 1, sub = nt & 1;
                    mma16816(acc[mt][nt], af[mt], bfq[ng][sub], bfq[ng][sub + 2]);
                }
        }
        // NOTE: no bottom barrier — the top-of-loop __syncthreads() (reached only
        // after every thread finishes this compute phase) orders reads of stage
        // (c%3) before the load_stage((c+3)%3 == c%3) issued in iteration c+1.
    }

    // ---- epilogue (fragment layout: lane = 4*g + tg; rows g, g+8; cols 2tg,2tg+1)
    const int g = lane >> 2, tg = lane & 3;
#pragma unroll
    for (int mt = 0; mt < 4; mt++) {
#pragma unroll
        for (int nt = 0; nt < 8; nt++) {
            const int row = m0 + wm + mt * 16 + g;
            const int col = n0 + wn + nt * 8 + 2 * tg;
            const long long o0 = (long long)row * N + col;
            const long long o1 = (long long)(row + 8) * N + col;
            float x0 = acc[mt][nt][0], x1 = acc[mt][nt][1];
            float x2 = acc[mt][nt][2], x3 = acc[mt][nt][3];
            if (BMODE == 1) {
                float b0 = bias[col], b1 = bias[col + 1];
                x0 += b0; x1 += b1; x2 += b0; x3 += b1;
            } else if (BMODE == 2) {
                float b0 = bias[row], b1 = bias[row + 8];
                x0 += b0; x1 += b0; x2 += b1; x3 += b1;
            }
            if (EPI == 0) {
                __nv_bfloat16* o = (__nv_bfloat16*)Out + (long long)b * sO;
                *(__nv_bfloat162*)(o + o0) = __floats2bfloat162_rn(x0, x1);
                *(__nv_bfloat162*)(o + o1) = __floats2bfloat162_rn(x2, x3);
            } else {
                float* o = (float*)Out + (long long)b * sO;
                if (EPI == 2) {
                    const float* rs = Res + (long long)b * sO;
                    float2 r0 = *(const float2*)(rs + o0);
                    float2 r1 = *(const float2*)(rs + o1);
                    x0 += r0.x; x1 += r0.y; x2 += r1.x; x3 += r1.y;
                }
                *(float2*)(o + o0) = make_float2(x0, x1);
                *(float2*)(o + o1) = make_float2(x2, x3);
            }
        }
    }
}

// ---------------- elementwise fp32 -> bf16 convert ---------------------------
__global__ __launch_bounds__(256) void cvt_bf16_kernel(const float4* __restrict__ in,
                                                       __nv_bfloat162* __restrict__ out,
                                                       int n4)
{
    int i = blockIdx.x * 256 + threadIdx.x;
    if (i < n4) {
        float4 v = in[i];
        out[2 * i]     = __floats2bfloat162_rn(v.x, v.y);
        out[2 * i + 1] = __floats2bfloat162_rn(v.z, v.w);
    }
}

// ---------------- tiled transpose (R,C) -> (C,R) bf16 ------------------------
__global__ __launch_bounds__(256)
void transpose_bf16_kernel(const float* __restrict__ in, __nv_bfloat16* __restrict__ out,
                           int R, int Cc, long long sIn, long long sOut)
{
    __shared__ float t[32][33];
    const int b = blockIdx.z;
    const float* I = in + sIn * b;
    __nv_bfloat16* O = out + sOut * b;
    const int c0 = blockIdx.x * 32, r0 = blockIdx.y * 32;
    const int tx = threadIdx.x & 31, ty = threadIdx.x >> 5;
#pragma unroll
    for (int i = 0; i < 32; i += 8)
        t[ty + i][tx] = I[(long long)(r0 + ty + i) * Cc + c0 + tx];
    __syncthreads();
#pragma unroll
    for (int i = 0; i < 32; i += 8)
        O[(long long)(c0 + ty + i) * R + r0 + tx] = __float2bfloat16(t[tx][ty + i]);
}

// ---------------- softmax(lam) -> g_w ; bqbk = bq.bk -------------------------
__global__ void prep_weights_kernel(const float* __restrict__ lam,
                                    const float* __restrict__ bq,
                                    const float* __restrict__ bk)
{
    const int lane = threadIdx.x;
    float s = 0.f;
    for (int c = lane; c < C_; c += 32) s += bq[c] * bk[c];
#pragma unroll
    for (int off = 16; off > 0; off >>= 1) s += __shfl_xor_sync(0xffffffffu, s, off);
    if (lane == 0) {
        g_bqbk = s;
        float m = fmaxf(lam[0], fmaxf(lam[1], lam[2]));
        float e0 = __expf(lam[0] - m);
        float e1 = __expf(lam[1] - m);
        float e2 = __expf(lam[2] - m);
        float t = e0 + e1 + e2;
        g_w[0] = e0 / t; g_w[1] = e1 / t; g_w[2] = e2 / t;
    }
}

// ---------------- out[r] = M[r,:] . v   (fp32, warp per row) -----------------
__global__ __launch_bounds__(256)
void dotrows_kernel(const float* __restrict__ M, const float* __restrict__ v,
                    float* __restrict__ out, int cols)
{
    int row = blockIdx.x * 8 + (threadIdx.x >> 5);
    int lane = threadIdx.x & 31;
    const float* mr = M + (long long)row * cols;
    float s = 0.f;
    for (int c = lane; c < cols; c += 32) s += mr[c] * v[c];
#pragma unroll
    for (int off = 16; off > 0; off >>= 1) s += __shfl_xor_sync(0xffffffffu, s, off);
    if (lane == 0) out[row] = s;
}

// ---------------- bias[b,l] = t_tok[b,l,:] . wkbq + bqbk ---------------------
__global__ __launch_bounds__(256) void bias_kernel(const float* __restrict__ t_tok)
{
    int row = blockIdx.x * 8 + (threadIdx.x >> 5);   // 0 .. B*L-1
    int lane = threadIdx.x & 31;
    const float* tr = t_tok + (long long)row * CT_;
    float s = 0.f;
    for (int c = lane; c < CT_; c += 32) s += tr[c] * g_wkbq[c];
#pragma unroll
    for (int off = 16; off > 0; off >>= 1) s += __shfl_xor_sync(0xffffffffu, s, off);
    if (lane == 0) g_bias[row] = s + g_bqbk;
}

// ============ fused box-pool (1/3/5) + 3-way softmax + combine ==============
// Block = (y, b). Reads bf16 logits (B,L,N), pools spatially on the fly,
// softmaxes over L per (scale, x), combines with weights -> attnT (B,N,L) bf16.
#define PS 50                       // plane column pad (48 -> 50)
#define PLANE (L_ * PS)             // 25600 bf16 per plane
#define SP_SMEM (3 * PLANE * 2 + 16 * 240 * 4)   // 168960 bytes

__global__ __launch_bounds__(512) void softmax_pool_kernel()
{
    extern __shared__ char sdyn[];
    __nv_bfloat16* planes = (__nv_bfloat16*)sdyn;                    // [3][L][PS]
    float* slab = (float*)(sdyn + 3 * PLANE * sizeof(__nv_bfloat16)); // [16][240]
    __shared__ float coef[NS_][48];

    const int b = blockIdx.y;
    const int y = blockIdx.x;
    const int tid = threadIdx.x, warp = tid >> 5, lane = tid & 31;
    const float sc = 0.03125f;      // C^{-1/2}

    float* ws = slab + warp * 240;  // 5 rows x 48 cols

    // ---- Phase A: pool + bias + scale, store 3 planes (bf16)
    for (int l = warp; l < L_; l += 16) {
        __syncwarp();
        const __nv_bfloat16* src = g_logits_bf + ((long long)(b * L_ + l)) * N_;
#pragma unroll
        for (int r = 0; r < 5; r++) {
            const int yy = y - 2 + r;
            if (lane < 12) {
                float4 o;
                if (yy >= 0 && yy < H_) {
                    uint2 u = *(const uint2*)(src + yy * W_ + lane * 4);
                    __nv_bfloat162 p0 = *(__nv_bfloat162*)&u.x;
                    __nv_bfloat162 p1 = *(__nv_bfloat162*)&u.y;
                    o.x = __bfloat162float(p0.x); o.y = __bfloat162float(p0.y);
                    o.z = __bfloat162float(p1.x); o.w = __bfloat162float(p1.y);
                } else {
                    o = make_float4(0.f, 0.f, 0.f, 0.f);
                }
                *(float4*)(ws + r * 48 + lane * 4) = o;
            }
        }
        __syncwarp();
        const float bias = g_bias[b * L_ + l];
        if (lane < 24) {
            const int x0 = lane * 2;
            float c0 = ws[96 + x0], c1 = ws[96 + x0 + 1];
            float s3a = 0.f, s3b = 0.f, s5a = 0.f, s5b = 0.f;
#pragma unroll
            for (int r = 0; r < 5; r++) {
                float v[6];
#pragma unroll
                for (int d = 0; d < 6; d++) {
                    const int xx = x0 - 2 + d;
                    v[d] = (xx >= 0 && xx < W_) ? ws[r * 48 + xx] : 0.f;
                }
                s5a += v[0] + v[1] + v[2] + v[3] + v[4];
                s5b += v[1] + v[2] + v[3] + v[4] + v[5];
                if (r >= 1 && r <= 3) {
                    s3a += v[1] + v[2] + v[3];
                    s3b += v[2] + v[3] + v[4];
                }
            }
            const int base = l * PS + x0;
            *(__nv_bfloat162*)(planes + 0 * PLANE + base) =
                __floats2bfloat162_rn((c0 + bias) * sc, (c1 + bias) * sc);
            *(__nv_bfloat162*)(planes + 1 * PLANE + base) =
                __floats2bfloat162_rn((s3a * (1.f / 9.f) + bias) * sc,
                                      (s3b * (1.f / 9.f) + bias) * sc);
            *(__nv_bfloat162*)(planes + 2 * PLANE + base) =
                __floats2bfloat162_rn((s5a * (1.f / 25.f) + bias) * sc,
                                      (s5b * (1.f / 25.f) + bias) * sc);
        }
    }
    __syncthreads();

    // ---- Phase B: per (scale, x) column softmax over L (warp per column)
    for (int col = warp; col < NS_ * 48; col += 16) {
        const int s = col / 48, x = col - s * 48;
        __nv_bfloat16* base = planes + s * PLANE + x;
        float vals[16];
        float mx = -1e30f;
#pragma unroll
        for (int r = 0; r < 16; r++) {
            vals[r] = __bfloat162float(base[(lane + r * 32) * PS]);
            mx = fmaxf(mx, vals[r]);
        }
#pragma unroll
        for (int off = 16; off > 0; off >>= 1)
            mx = fmaxf(mx, __shfl_xor_sync(0xffffffffu, mx, off));
        float ssum = 0.f;
#pragma unroll
        for (int r = 0; r < 16; r++) {
            float e = __expf(vals[r] - mx);
            base[(lane + r * 32) * PS] = __float2bfloat16(e);
            ssum += e;
        }
#pragma unroll
        for (int off = 16; off > 0; off >>= 1)
            ssum += __shfl_xor_sync(0xffffffffu, ssum, off);
        if (lane == 0) coef[s][x] = g_w[s] / ssum;
    }
    __syncthreads();

    // ---- Phase C: weighted combine -> attnT (B, N, L) bf16
    for (int x = warp; x < 48; x += 16) {
        const float c0 = coef[0][x], c1 = coef[1][x], c2 = coef[2][x];
        __nv_bfloat16* dst = g_attnT_bf + ((long long)(b * N_ + y * W_ + x)) * L_;
        for (int l = lane; l < L_; l += 32) {
            const int base = l * PS + x;
            float v = __bfloat162float(planes[0 * PLANE + base]) * c0
                    + __bfloat162float(planes[1 * PLANE + base]) * c1
                    + __bfloat162float(planes[2 * PLANE + base]) * c2;
            dst[l] = __float2bfloat16(v);
        }
    }
}

// ---------------- t_tok passthrough -----------------------------------------
__global__ __launch_bounds__(256) void copy_kernel(const float4* __restrict__ src,
                                                   float4* __restrict__ dst, int n4)
{
    int i = blockIdx.x * 256 + threadIdx.x;
    if (i < n4) dst[i] = src[i];
}

// ---------------- host ------------------------------------------------------
extern "C" void kernel_launch(void* const* d_in, const int* in_sizes, int n_in,
                              void* d_out, int out_size)
{
    const float* v_feat = (const float*)d_in[0];   // (B,C,H,W)
    const float* t_tok  = (const float*)d_in[1];   // (B,L,Ct)
    const float* Wq     = (const float*)d_in[2];   // (C,C)
    const float* bq     = (const float*)d_in[3];
    const float* Wk     = (const float*)d_in[4];   // (Ct,C)
    const float* bk     = (const float*)d_in[5];
    const float* Wv     = (const float*)d_in[6];   // (Ct,C)
    const float* bv     = (const float*)d_in[7];
    const float* lam    = (const float*)d_in[8];   // (3,)
    float* out = (float*)d_out;

    __nv_bfloat16 *p_ttok, *p_Wq, *p_Wk, *p_WvT, *p_WkqT, *p_vtxtT, *p_vflat,
                  *p_kq, *p_attnT, *p_logits;
    float *p_wkbq, *p_bkq;
    cudaGetSymbolAddress((void**)&p_ttok,  g_ttok_bf);
    cudaGetSymbolAddress((void**)&p_Wq,    g_Wq_bf);
    cudaGetSymbolAddress((void**)&p_Wk,    g_Wk_bf);
    cudaGetSymbolAddress((void**)&p_WvT,   g_WvT);
    cudaGetSymbolAddress((void**)&p_WkqT,  g_WkqT);
    cudaGetSymbolAddress((void**)&p_vtxtT, g_vtxtT_bf);
    cudaGetSymbolAddress((void**)&p_vflat, g_vflat_bf);
    cudaGetSymbolAddress((void**)&p_kq,    g_kq_bf);
    cudaGetSymbolAddress((void**)&p_attnT, g_attnT_bf);
    cudaGetSymbolAddress((void**)&p_logits, g_logits_bf);
    cudaGetSymbolAddress((void**)&p_wkbq,  g_wkbq);
    cudaGetSymbolAddress((void**)&p_bkq,   g_bkq);

    cudaFuncSetAttribute(mm_bf16<0, 0>, cudaFuncAttributeMaxDynamicSharedMemorySize, MM_SMEM);
    cudaFuncSetAttribute(mm_bf16<0, 1>, cudaFuncAttributeMaxDynamicSharedMemorySize, MM_SMEM);
    cudaFuncSetAttribute(mm_bf16<0, 2>, cudaFuncAttributeMaxDynamicSharedMemorySize, MM_SMEM);
    cudaFuncSetAttribute(mm_bf16<2, 0>, cudaFuncAttributeMaxDynamicSharedMemorySize, MM_SMEM);
    cudaFuncSetAttribute(softmax_pool_kernel,
                         cudaFuncAttributeMaxDynamicSharedMemorySize, SP_SMEM);

    prep_weights_kernel<<<1, 32>>>(lam, bq, bk);

    // bf16 conversions (original layouts)
    {
        int n4 = (B_ * L_ * CT_) / 4;
        cvt_bf16_kernel<<<(n4 + 255) / 256, 256>>>((const float4*)t_tok,
                                                   (__nv_bfloat162*)p_ttok, n4);
        int w4 = (C_ * C_) / 4;
        cvt_bf16_kernel<<<(w4 + 255) / 256, 256>>>((const float4*)Wq,
                                                   (__nv_bfloat162*)p_Wq, w4);
        int k4 = (CT_ * C_) / 4;
        cvt_bf16_kernel<<<(k4 + 255) / 256, 256>>>((const float4*)Wk,
                                                   (__nv_bfloat162*)p_Wk, k4);
    }
    // Wv -> WvT bf16 (C, Ct)
    transpose_bf16_kernel<<<dim3(C_ / 32, CT_ / 32, 1), 256>>>(Wv, p_WvT, CT_, C_, 0, 0);
    // v_feat (B,C,N) -> v_flat (B,N,C) bf16
    transpose_bf16_kernel<<<dim3(N_ / 32, C_ / 32, B_), 256>>>(
        v_feat, p_vflat, C_, N_, (long long)C_ * N_, (long long)N_ * C_);

    // vector precomputes (exact fp32)
    dotrows_kernel<<<CT_ / 8, 256>>>(Wk, bq, p_wkbq, C_);   // wkbq[ct] = Wk[ct,:].bq
    dotrows_kernel<<<C_ / 8, 256>>>(Wq, bk, p_bkq, C_);     // bkq[cin] = Wq[cin,:].bk
    bias_kernel<<<(B_ * L_) / 8, 256>>>(t_tok);             // bias = t_tok.wkbq + bq.bk

    // WkqT[cin, ct] = sum_cout Wq[cin,cout] * Wk[ct,cout]   (M=C, N=Ct, K=C)
    mm_bf16<0, 0><<<dim3(CT_ / BN, C_ / BM, 1), 256, MM_SMEM>>>(
        p_Wq, p_Wk, p_WkqT, nullptr, nullptr, CT_, C_, 0, 0, 0);

    // kq = t_tok @ WkqT^T + bkq  -> bf16 (B*L, C)   (M=B*L, N=C, K=Ct)
    mm_bf16<0, 1><<<dim3(C_ / BN, (B_ * L_) / BM, 1), 256, MM_SMEM>>>(
        p_ttok, p_WkqT, p_kq, p_bkq, nullptr, C_, CT_, 0, 0, 0);

    // vtxtT[b] = WvT @ t_tok[b]^T + bv (row bias) -> bf16 (B,C,L)  (M=C,N=L,K=Ct)
    mm_bf16<0, 2><<<dim3(L_ / BN, C_ / BM, B_), 256, MM_SMEM>>>(
        p_WvT, p_ttok, p_vtxtT, bv, nullptr, L_, CT_,
        0, (long long)L_ * CT_, (long long)C_ * L_);

    // logits[b] = kq[b] @ v_flat[b]^T  -> bf16 (B,L,N)
    mm_bf16<0, 0><<<dim3(N_ / BN, L_ / BM, B_), 256, MM_SMEM>>>(
        p_kq, p_vflat, p_logits, nullptr, nullptr, N_, C_,
        (long long)L_ * C_, (long long)N_ * C_, (long long)L_ * N_);

    // fused pool + softmax + combine -> attnT (B,N,L) bf16
    softmax_pool_kernel<<<dim3(H_, B_), 512, SP_SMEM>>>();

    // out_vis[b] = v_txt[b]^T @ attn[b] + v_feat[b]  -> fp32 (B,C,N)
    mm_bf16<2, 0><<<dim3(N_ / BN, C_ / BM, B_), 256, MM_SMEM>>>(
        p_vtxtT, p_attnT, out, nullptr, v_feat, N_, L_,
        (long long)C_ * L_, (long long)N_ * L_, (long long)C_ * N_);

    // t_tok passthrough
    int n4 = (B_ * L_ * CT_) / 4;
    copy_kernel<<<(n4 + 255) / 256, 256>>>(
        (const float4*)t_tok, (float4*)(out + (size_t)B_ * C_ * N_), n4);
}